// round 11
// baseline (speedup 1.0000x reference)
#include <cuda_runtime.h>
#include <cuda_bf16.h>
#include <math_constants.h>
#include <cstdint>

#define NN      100000
#define EE      3200000
#define CYD     128
#define H1      512
#define FD      10
#define HC      20
#define H2      512

// ---------------- device scratch ----------------
__device__ float    g_xl[NN * HC];
__device__ float    g_xr[NN * HC];
__device__ float    g_den[NN * 2];
__device__ float    g_num[NN * HC];
__device__ int      g_mask_mode;
__device__ int      g_nu, g_nm;
__device__ int      g_perm[NN];
__device__ int      g_mlist[NN];
__device__ uint32_t g_w1frag[(H1 / 8) * (CYD / 16) * 32 * 4];
__device__ uint32_t g_w3frag[(H2 / 8) * (32 / 16) * 32 * 4];
__device__ uint32_t g_w4frag[(CYD / 8) * (H2 / 16) * 32 * 4];

// ---------------- helpers ----------------
__device__ __forceinline__ unsigned long long pack2(float a, float b) {
    unsigned long long r;
    asm("mov.b64 %0, {%1, %2};" : "=l"(r) : "f"(a), "f"(b));
    return r;
}
__device__ __forceinline__ float2 unpack2(unsigned long long v) {
    float2 r;
    asm("mov.b64 {%0, %1}, %2;" : "=f"(r.x), "=f"(r.y) : "l"(v));
    return r;
}
__device__ __forceinline__ void fma2(unsigned long long& acc,
                                     unsigned long long a, unsigned long long b) {
    asm("fma.rn.f32x2 %0, %1, %2, %0;" : "+l"(acc) : "l"(a), "l"(b));
}
__device__ __forceinline__ uint32_t pk_bf2(float a, float b) {
    __nv_bfloat162 h = __floats2bfloat162_rn(a, b);
    return *(uint32_t*)&h;
}
__device__ __forceinline__ void mma_bf16(float* c, const uint32_t* a, uint32_t b0, uint32_t b1) {
    asm volatile("mma.sync.aligned.m16n8k16.row.col.f32.bf16.bf16.f32 "
                 "{%0,%1,%2,%3}, {%4,%5,%6,%7}, {%8,%9}, {%0,%1,%2,%3};"
                 : "+f"(c[0]), "+f"(c[1]), "+f"(c[2]), "+f"(c[3])
                 : "r"(a[0]), "r"(a[1]), "r"(a[2]), "r"(a[3]), "r"(b0), "r"(b1));
}

// ---------------- mask dtype detection + counter reset ----------------
__global__ void k_detect(const unsigned* __restrict__ mw) {
    __shared__ int notInt, notFloat;
    if (threadIdx.x == 0) { notInt = 0; notFloat = 0; g_nu = 0; g_nm = 0; }
    __syncthreads();
    unsigned v = mw[threadIdx.x];
    if (v > 1u)                      atomicOr(&notInt, 1);
    if (v != 0u && v != 0x3f800000u) atomicOr(&notFloat, 1);
    __syncthreads();
    if (threadIdx.x == 0)
        g_mask_mode = notInt ? (notFloat ? 0 : 2) : 1;
}

// ---------------- init + node compaction (order-free), merged ----------------
__global__ void k_initcompact(const void* __restrict__ mask) {
    int i = blockIdx.x * blockDim.x + threadIdx.x;
    if (i < NN * HC) g_num[i] = 0.f;
    if (i < NN * 2) g_den[i] = 0.f;
    if (i < NN) {
        int mode = g_mask_mode;
        bool mk;
        if (mode == 0)      mk = ((const unsigned char*)mask)[i] != 0;
        else if (mode == 1) mk = ((const int*)mask)[i] != 0;
        else                mk = ((const float*)mask)[i] != 0.f;
        if (!mk) g_perm[atomicAdd(&g_nu, 1)] = i;
        else     g_mlist[atomicAdd(&g_nm, 1)] = i;
    }
}

// ---------------- merged weight fragment prep ----------------
__device__ __forceinline__ void prep_one(const float* W, uint32_t* frag,
                                         int Kreal, int Kpad, int Nn, int i)
{
    int kp2 = Kpad >> 1;
    if (i >= Nn * kp2) return;
    int n = i / kp2, k = (i % kp2) * 2;
    float w0 = (k     < Kreal) ? W[(size_t)k * Nn + n]       : 0.f;
    float w1 = (k + 1 < Kreal) ? W[(size_t)(k + 1) * Nn + n] : 0.f;
    float h0f = __bfloat162float(__float2bfloat16(w0));
    float h1f = __bfloat162float(__float2bfloat16(w1));
    uint32_t whi = pk_bf2(h0f, h1f);
    uint32_t wlo = pk_bf2(w0 - h0f, w1 - h1f);
    int n8 = n >> 3, ks = k >> 4;
    int lane = ((n & 7) << 2) | ((k & 7) >> 1);
    int b01 = (k >> 3) & 1;
    int base = ((n8 * (Kpad >> 4) + ks) * 32 + lane) * 4;
    frag[base + b01]     = whi;
    frag[base + 2 + b01] = wlo;
}

// blocks [0,128): W1 ; [128,160): W3 ; [160,288): W4
__global__ void k_prep_all(const float* __restrict__ W1,
                           const float* __restrict__ W3,
                           const float* __restrict__ W4,
                           uint32_t* __restrict__ w1f,
                           uint32_t* __restrict__ w3f,
                           uint32_t* __restrict__ w4f)
{
    int b = blockIdx.x;
    if (b < 128)      prep_one(W1, w1f, CYD, CYD, H1, b * 256 + threadIdx.x);
    else if (b < 160) prep_one(W3, w3f, HC, 32, H2, (b - 128) * 256 + threadIdx.x);
    else              prep_one(W4, w4f, H2, H2, CYD, (b - 160) * 256 + threadIdx.x);
}

// ---------------- masked-node constant fill ----------------
__global__ void __launch_bounds__(256)
k_fill(const float* __restrict__ b1, const float* __restrict__ gamma,
       const float* __restrict__ beta, const float* __restrict__ W2,
       const float* __restrict__ b2,
       const float* __restrict__ Wl, const float* __restrict__ bl,
       const float* __restrict__ Wr, const float* __restrict__ br)
{
    __shared__ float sh[H1];
    __shared__ float sx2[FD];
    __shared__ __align__(16) float sout[2 * HC];
    const int t = threadIdx.x;
    const float inv = rsqrtf(1.f + 1e-5f);
    for (int h = t; h < H1; h += 256)
        sh[h] = fmaxf(b1[h] * gamma[h] * inv + beta[h], 0.f);
    __syncthreads();
    if (t < FD) {
        float a = b2[t];
        for (int h = 0; h < H1; h++) a += sh[h] * W2[h * FD + t];
        sx2[t] = a;
    }
    __syncthreads();
    if (t < 2 * HC) {
        int j = t % HC;
        bool left = t < HC;
        const float* W = left ? Wl : Wr;
        float a = left ? bl[j] : br[j];
        #pragma unroll
        for (int k = 0; k < FD; k++) a += sx2[k] * W[k * HC + j];
        sout[t] = a;
    }
    __syncthreads();
    const int nm = g_nm;
    for (int i = blockIdx.x * 256 + t; i < nm; i += gridDim.x * 256) {
        int node = g_mlist[i];
        float4* pl = (float4*)&g_xl[(size_t)node * HC];
        float4* pr = (float4*)&g_xr[(size_t)node * HC];
        #pragma unroll
        for (int q = 0; q < 5; q++) {
            pl[q] = *(float4*)&sout[q * 4];
            pr[q] = *(float4*)&sout[HC + q * 4];
        }
    }
}

// =====================================================================
// kernel A: compact rows -> GEMM1(mma bf16 3-pass) -> BN -> ReLU
//           -> GEMM2 -> fused xl/xr epilogue
// =====================================================================
#define A_STRIDE 136
#define OFF_AHI  0
#define OFF_ALO  34816
#define OFF_HSF  69632
#define OFF_W2T  135168
#define OFF_B1   155648
#define OFF_SC   157696
#define OFF_BE   159744
#define OFF_WLR  161792
#define SM1_TOTAL 163584

__global__ void __launch_bounds__(256, 1)
k_mlp_mma(const float* __restrict__ signal,
          const float* __restrict__ W2, const float* __restrict__ b1,
          const float* __restrict__ gamma, const float* __restrict__ beta,
          const float* __restrict__ b2,
          const float* __restrict__ Wl, const float* __restrict__ bl,
          const float* __restrict__ Wr, const float* __restrict__ br)
{
    extern __shared__ char smem[];
    const int nu = g_nu;
    const int row0 = blockIdx.x * 128;
    if (row0 >= nu) return;

    __nv_bfloat16* Ahi = (__nv_bfloat16*)(smem + OFF_AHI);
    __nv_bfloat16* Alo = (__nv_bfloat16*)(smem + OFF_ALO);
    float2* hsf2 = (float2*)(smem + OFF_HSF);
    float*  x2s  = (float*)(smem + OFF_HSF);
    float*  w2t  = (float*)(smem + OFF_W2T);
    float*  sb1  = (float*)(smem + OFF_B1);
    float*  ssc  = (float*)(smem + OFF_SC);
    float*  sbe  = (float*)(smem + OFF_BE);
    float*  sWl  = (float*)(smem + OFF_WLR);
    float*  sWr  = sWl + 200;
    float*  sbl  = sWr + 200;
    float*  sbr  = sbl + 20;

    const int tid = threadIdx.x;
    const int lane = tid & 31;
    const int wid  = tid >> 5;
    const int wm = wid & 3, wn = wid >> 2;
    const int g  = lane >> 2, q4 = lane & 3;

    const float inv = rsqrtf(1.f + 1e-5f);
    for (int i = tid; i < H1; i += 256) {
        sb1[i] = b1[i];
        ssc[i] = gamma[i] * inv;
        sbe[i] = beta[i];
    }
    for (int i = tid; i < H1 * FD; i += 256) {
        int c = i / H1, k = i % H1;
        w2t[c * H1 + k] = W2[(size_t)k * FD + c];
    }
    if (tid < 200) { sWl[tid] = Wl[tid]; sWr[tid] = Wr[tid]; }
    else if (tid < 220) sbl[tid - 200] = bl[tid - 200];
    else if (tid < 240) sbr[tid - 220] = br[tid - 220];

    {
        const int r = tid >> 1, ch = tid & 1;
        const int idx = row0 + r;
        const bool ok = (idx < nu);
        const int n = ok ? g_perm[idx] : 0;
        const float4* xp = (const float4*)&signal[(size_t)n * CYD + ch * 64];
        #pragma unroll
        for (int qq = 0; qq < 8; qq++) {
            float4 v0 = ok ? xp[2 * qq]     : make_float4(0, 0, 0, 0);
            float4 v1 = ok ? xp[2 * qq + 1] : make_float4(0, 0, 0, 0);
            float f[8] = { v0.x, v0.y, v0.z, v0.w, v1.x, v1.y, v1.z, v1.w };
            float fh[8];
            #pragma unroll
            for (int u = 0; u < 8; u++) fh[u] = __bfloat162float(__float2bfloat16(f[u]));
            uint4 hi = make_uint4(pk_bf2(fh[0], fh[1]), pk_bf2(fh[2], fh[3]),
                                  pk_bf2(fh[4], fh[5]), pk_bf2(fh[6], fh[7]));
            uint4 lo = make_uint4(pk_bf2(f[0] - fh[0], f[1] - fh[1]), pk_bf2(f[2] - fh[2], f[3] - fh[3]),
                                  pk_bf2(f[4] - fh[4], f[5] - fh[5]), pk_bf2(f[6] - fh[6], f[7] - fh[7]));
            int eoff = r * A_STRIDE + ch * 64 + qq * 8;
            *(uint4*)&Ahi[eoff] = hi;
            *(uint4*)&Alo[eoff] = lo;
        }
    }
    __syncthreads();

    unsigned long long acc2[5];
    #pragma unroll
    for (int j = 0; j < 5; j++) acc2[j] = 0ull;
    const int r2 = tid & 127, grp = tid >> 7;

    for (int nt = 0; nt < 4; nt++) {
        float acc[2][8][4];
        #pragma unroll
        for (int mt = 0; mt < 2; mt++)
            #pragma unroll
            for (int j = 0; j < 8; j++)
                #pragma unroll
                for (int c = 0; c < 4; c++) acc[mt][j][c] = 0.f;

        #pragma unroll
        for (int ks = 0; ks < 8; ks++) {
            const int k0 = ks * 16 + q4 * 2;
            uint32_t ah[2][4], al[2][4];
            #pragma unroll
            for (int mt = 0; mt < 2; mt++) {
                int ra = wm * 32 + mt * 16 + g;
                ah[mt][0] = *(const uint32_t*)&Ahi[ra * A_STRIDE + k0];
                ah[mt][1] = *(const uint32_t*)&Ahi[(ra + 8) * A_STRIDE + k0];
                ah[mt][2] = *(const uint32_t*)&Ahi[ra * A_STRIDE + k0 + 8];
                ah[mt][3] = *(const uint32_t*)&Ahi[(ra + 8) * A_STRIDE + k0 + 8];
                al[mt][0] = *(const uint32_t*)&Alo[ra * A_STRIDE + k0];
                al[mt][1] = *(const uint32_t*)&Alo[(ra + 8) * A_STRIDE + k0];
                al[mt][2] = *(const uint32_t*)&Alo[ra * A_STRIDE + k0 + 8];
                al[mt][3] = *(const uint32_t*)&Alo[(ra + 8) * A_STRIDE + k0 + 8];
            }
            #pragma unroll
            for (int j = 0; j < 8; j++) {
                int n8 = nt * 16 + wn * 8 + j;
                const uint4 bv = *(const uint4*)&g_w1frag[((n8 * 8 + ks) * 32 + lane) * 4];
                #pragma unroll
                for (int mt = 0; mt < 2; mt++) {
                    mma_bf16(acc[mt][j], ah[mt], bv.x, bv.y);
                    mma_bf16(acc[mt][j], ah[mt], bv.z, bv.w);
                    mma_bf16(acc[mt][j], al[mt], bv.x, bv.y);
                }
            }
        }

        #pragma unroll
        for (int j = 0; j < 8; j++) {
            int hcol = nt * 128 + wn * 64 + j * 8 + q4 * 2;
            float s0 = ssc[hcol], s1 = ssc[hcol + 1];
            float bi0 = sb1[hcol], bi1 = sb1[hcol + 1];
            float be0 = sbe[hcol], be1 = sbe[hcol + 1];
            int cp = wn * 32 + j * 4 + q4;
            #pragma unroll
            for (int mt = 0; mt < 2; mt++) {
                int ra = wm * 32 + mt * 16 + g;
                float v0 = fmaxf((acc[mt][j][0] + bi0) * s0 + be0, 0.f);
                float v1 = fmaxf((acc[mt][j][1] + bi1) * s1 + be1, 0.f);
                float v2 = fmaxf((acc[mt][j][2] + bi0) * s0 + be0, 0.f);
                float v3 = fmaxf((acc[mt][j][3] + bi1) * s1 + be1, 0.f);
                hsf2[cp * 128 + ra]     = make_float2(v0, v1);
                hsf2[cp * 128 + ra + 8] = make_float2(v2, v3);
            }
        }
        __syncthreads();

        {
            #pragma unroll 8
            for (int cp = 0; cp < 64; cp++) {
                float2 h = hsf2[cp * 128 + r2];
                unsigned long long hp = pack2(h.x, h.y);
                #pragma unroll
                for (int j = 0; j < 5; j++) {
                    const float2 w = *(const float2*)&w2t[(grp * 5 + j) * H1 + nt * 128 + cp * 2];
                    fma2(acc2[j], hp, pack2(w.x, w.y));
                }
            }
        }
        __syncthreads();
    }

    #pragma unroll
    for (int j = 0; j < 5; j++) {
        float2 u = unpack2(acc2[j]);
        x2s[r2 * 13 + grp * 5 + j] = u.x + u.y + b2[grp * 5 + j];
    }
    __syncthreads();

    {
        const int idx = row0 + r2;
        if (idx < nu) {
            const int node = g_perm[idx];
            float x10[FD];
            #pragma unroll
            for (int k = 0; k < FD; k++) x10[k] = x2s[r2 * 13 + k];
            const float* W  = grp ? sWr : sWl;
            const float* bb = grp ? sbr : sbl;
            float o[HC];
            #pragma unroll
            for (int j = 0; j < HC; j++) {
                float a = bb[j];
                #pragma unroll
                for (int k = 0; k < FD; k++) a += x10[k] * W[k * HC + j];
                o[j] = a;
            }
            float* dst = grp ? &g_xr[(size_t)node * HC] : &g_xl[(size_t)node * HC];
            #pragma unroll
            for (int q = 0; q < 5; q++)
                *(float4*)&dst[q * 4] = make_float4(o[q*4], o[q*4+1], o[q*4+2], o[q*4+3]);
        }
    }
}

// ---------------- fused edge pass: alpha -> exp -> scatter num/den ----------------
__global__ void __launch_bounds__(256)
k_edge(const int* __restrict__ ei, const float* __restrict__ ew,
       const float* __restrict__ We, const float* __restrict__ att)
{
    __shared__ float sWe[HC], sAtt[HC];
    if (threadIdx.x < HC)            sWe[threadIdx.x] = We[threadIdx.x];
    else if (threadIdx.x < 2 * HC)   sAtt[threadIdx.x - HC] = att[threadIdx.x - HC];
    __syncthreads();

    int e = blockIdx.x * blockDim.x + threadIdx.x;
    if (e >= EE) return;
    int src = ei[e], dst = ei[EE + e];
    float w = ew[e];
    const float4* xl4 = (const float4*)&g_xl[src * HC];
    const float4* xr4 = (const float4*)&g_xr[dst * HC];
    float xlv[HC];
    float a0 = 0.f, a1 = 0.f;
    #pragma unroll
    for (int q = 0; q < 5; q++) {
        float4 l = xl4[q], r = xr4[q];
        xlv[q * 4 + 0] = l.x; xlv[q * 4 + 1] = l.y;
        xlv[q * 4 + 2] = l.z; xlv[q * 4 + 3] = l.w;
        float vv[4] = { l.x + r.x, l.y + r.y, l.z + r.z, l.w + r.w };
        #pragma unroll
        for (int u = 0; u < 4; u++) {
            int j = q * 4 + u;
            float v = vv[u] + w * sWe[j];
            v = v > 0.f ? v : 0.2f * v;
            if (j < 10) a0 += v * sAtt[j];
            else        a1 += v * sAtt[j];
        }
    }
    float ex0 = __expf(a0), ex1 = __expf(a1);
    asm volatile("red.global.add.v2.f32 [%0], {%1,%2};"
                 :: "l"(&g_den[dst * 2]), "f"(ex0), "f"(ex1) : "memory");
    float* np = &g_num[dst * HC];
    #pragma unroll
    for (int q = 0; q < 5; q++) {
        float sx = (q * 4 + 0 < 10) ? ex0 : ex1;
        float sy = (q * 4 + 1 < 10) ? ex0 : ex1;
        float sz = (q * 4 + 2 < 10) ? ex0 : ex1;
        float sw = (q * 4 + 3 < 10) ? ex0 : ex1;
        float4 v = make_float4(xlv[q * 4] * sx, xlv[q * 4 + 1] * sy,
                               xlv[q * 4 + 2] * sz, xlv[q * 4 + 3] * sw);
        asm volatile("red.global.add.v4.f32 [%0], {%1,%2,%3,%4};"
                     :: "l"(np + q * 4), "f"(v.x), "f"(v.y), "f"(v.z), "f"(v.w)
                     : "memory");
    }
}

// =====================================================================
// kernel D: normalize -> +gat_bias -> GEMM3(mma) -> GEMM4(mma) -> out
// =====================================================================
#define A3_STRIDE 40
#define H_STRIDE  136
#define OFF_A3H   0
#define OFF_A3L   10240
#define OFF_HH    20480
#define OFF_HL    55296
#define SM2_TOTAL 90112

__global__ void __launch_bounds__(256, 1)
k_out_mma(const float* __restrict__ gat_bias,
          const float* __restrict__ b3, const float* __restrict__ b4,
          float* __restrict__ out)
{
    extern __shared__ char smem[];
    __nv_bfloat16* A3h = (__nv_bfloat16*)(smem + OFF_A3H);
    __nv_bfloat16* A3l = (__nv_bfloat16*)(smem + OFF_A3L);
    __nv_bfloat16* Hh  = (__nv_bfloat16*)(smem + OFF_HH);
    __nv_bfloat16* Hl  = (__nv_bfloat16*)(smem + OFF_HL);

    const int tid = threadIdx.x;
    const int lane = tid & 31;
    const int wid  = tid >> 5;
    const int wm = wid & 3, wn = wid >> 2;
    const int g = lane >> 2, q4 = lane & 3;
    const int row0 = blockIdx.x * 128;

    for (int i = tid; i < 128 * 32; i += 256) {
        int r = i >> 5, c = i & 31;
        A3h[r * A3_STRIDE + c] = __float2bfloat16(0.f);
        A3l[r * A3_STRIDE + c] = __float2bfloat16(0.f);
    }
    __syncthreads();
    for (int i = tid; i < 128 * HC; i += 256) {
        int r = i / HC, c = i % HC;
        int n = row0 + r;
        float v = 0.f;
        if (n < NN)
            v = g_num[(size_t)n * HC + c] / (g_den[n * 2 + c / 10] + 1e-16f) + gat_bias[c];
        __nv_bfloat16 h = __float2bfloat16(v);
        A3h[r * A3_STRIDE + c] = h;
        A3l[r * A3_STRIDE + c] = __float2bfloat16(v - __bfloat162float(h));
    }
    __syncthreads();

    float2 bw[8];
    #pragma unroll
    for (int j = 0; j < 8; j++)
        bw[j] = *(const float2*)&b4[wn * 64 + j * 8 + q4 * 2];

    float acc4[2][8][4];
    #pragma unroll
    for (int mt = 0; mt < 2; mt++)
        #pragma unroll
        for (int j = 0; j < 8; j++)
            #pragma unroll
            for (int c = 0; c < 4; c++) acc4[mt][j][c] = 0.f;

    for (int nt = 0; nt < 4; nt++) {
        float acc3[2][8][4];
        #pragma unroll
        for (int mt = 0; mt < 2; mt++)
            #pragma unroll
            for (int j = 0; j < 8; j++)
                #pragma unroll
                for (int c = 0; c < 4; c++) acc3[mt][j][c] = 0.f;

        #pragma unroll
        for (int ks = 0; ks < 2; ks++) {
            const int k0 = ks * 16 + q4 * 2;
            uint32_t ah[2][4], al[2][4];
            #pragma unroll
            for (int mt = 0; mt < 2; mt++) {
                int ra = wm * 32 + mt * 16 + g;
                ah[mt][0] = *(const uint32_t*)&A3h[ra * A3_STRIDE + k0];
                ah[mt][1] = *(const uint32_t*)&A3h[(ra + 8) * A3_STRIDE + k0];
                ah[mt][2] = *(const uint32_t*)&A3h[ra * A3_STRIDE + k0 + 8];
                ah[mt][3] = *(const uint32_t*)&A3h[(ra + 8) * A3_STRIDE + k0 + 8];
                al[mt][0] = *(const uint32_t*)&A3l[ra * A3_STRIDE + k0];
                al[mt][1] = *(const uint32_t*)&A3l[(ra + 8) * A3_STRIDE + k0];
                al[mt][2] = *(const uint32_t*)&A3l[ra * A3_STRIDE + k0 + 8];
                al[mt][3] = *(const uint32_t*)&A3l[(ra + 8) * A3_STRIDE + k0 + 8];
            }
            #pragma unroll
            for (int j = 0; j < 8; j++) {
                int n8 = nt * 16 + wn * 8 + j;
                const uint4 bv = *(const uint4*)&g_w3frag[((n8 * 2 + ks) * 32 + lane) * 4];
                #pragma unroll
                for (int mt = 0; mt < 2; mt++) {
                    mma_bf16(acc3[mt][j], ah[mt], bv.x, bv.y);
                    mma_bf16(acc3[mt][j], ah[mt], bv.z, bv.w);
                    mma_bf16(acc3[mt][j], al[mt], bv.x, bv.y);
                }
            }
        }

        #pragma unroll
        for (int j = 0; j < 8; j++) {
            int hcol = nt * 128 + wn * 64 + j * 8 + q4 * 2;
            float2 bb = *(const float2*)&b3[hcol];
            int cl = wn * 64 + j * 8 + q4 * 2;
            #pragma unroll
            for (int mt = 0; mt < 2; mt++) {
                int ra = wm * 32 + mt * 16 + g;
                float v0 = acc3[mt][j][0] + bb.x;
                float v1 = acc3[mt][j][1] + bb.y;
                float v2 = acc3[mt][j][2] + bb.x;
                float v3 = acc3[mt][j][3] + bb.y;
                float h0 = __bfloat162float(__float2bfloat16(v0));
                float h1 = __bfloat162float(__float2bfloat16(v1));
                float h2 = __bfloat162float(__float2bfloat16(v2));
                float h3 = __bfloat162float(__float2bfloat16(v3));
                *(uint32_t*)&Hh[ra * H_STRIDE + cl]       = pk_bf2(h0, h1);
                *(uint32_t*)&Hh[(ra + 8) * H_STRIDE + cl] = pk_bf2(h2, h3);
                *(uint32_t*)&Hl[ra * H_STRIDE + cl]       = pk_bf2(v0 - h0, v1 - h1);
                *(uint32_t*)&Hl[(ra + 8) * H_STRIDE + cl] = pk_bf2(v2 - h2, v3 - h3);
            }
        }
        __syncthreads();

        #pragma unroll
        for (int ks = 0; ks < 8; ks++) {
            const int k0 = ks * 16 + q4 * 2;
            uint32_t ah[2][4], al[2][4];
            #pragma unroll
            for (int mt = 0; mt < 2; mt++) {
                int ra = wm * 32 + mt * 16 + g;
                ah[mt][0] = *(const uint32_t*)&Hh[ra * H_STRIDE + k0];
                ah[mt][1] = *(const uint32_t*)&Hh[(ra + 8) * H_STRIDE + k0];
                ah[mt][2] = *(const uint32_t*)&Hh[ra * H_STRIDE + k0 + 8];
                ah[mt][3] = *(const uint32_t*)&Hh[(ra + 8) * H_STRIDE + k0 + 8];
                al[mt][0] = *(const uint32_t*)&Hl[ra * H_STRIDE + k0];
                al[mt][1] = *(const uint32_t*)&Hl[(ra + 8) * H_STRIDE + k0];
                al[mt][2] = *(const uint32_t*)&Hl[ra * H_STRIDE + k0 + 8];
                al[mt][3] = *(const uint32_t*)&Hl[(ra + 8) * H_STRIDE + k0 + 8];
            }
            #pragma unroll
            for (int j = 0; j < 8; j++) {
                int n8 = wn * 8 + j;
                int ksg = nt * 8 + ks;
                const uint4 bv = *(const uint4*)&g_w4frag[((n8 * 32 + ksg) * 32 + lane) * 4];
                #pragma unroll
                for (int mt = 0; mt < 2; mt++) {
                    mma_bf16(acc4[mt][j], ah[mt], bv.x, bv.y);
                    mma_bf16(acc4[mt][j], ah[mt], bv.z, bv.w);
                    mma_bf16(acc4[mt][j], al[mt], bv.x, bv.y);
                }
            }
        }
        __syncthreads();
    }

    #pragma unroll
    for (int j = 0; j < 8; j++) {
        int col = wn * 64 + j * 8 + q4 * 2;
        #pragma unroll
        for (int mt = 0; mt < 2; mt++) {
            int ra = row0 + wm * 32 + mt * 16 + g;
            if (ra < NN)
                *(float2*)&out[(size_t)ra * CYD + col] =
                    make_float2(acc4[mt][j][0] + bw[j].x, acc4[mt][j][1] + bw[j].y);
            if (ra + 8 < NN)
                *(float2*)&out[(size_t)(ra + 8) * CYD + col] =
                    make_float2(acc4[mt][j][2] + bw[j].x, acc4[mt][j][3] + bw[j].y);
        }
    }
}

// ---------------- launch ----------------
extern "C" void kernel_launch(void* const* d_in, const int* in_sizes, int n_in,
                              void* d_out, int out_size)
{
    const float* signal = (const float*)d_in[0];
    const int*   ei     = (const int*)  d_in[1];
    const float* ew     = (const float*)d_in[2];
    const void*  mask   =               d_in[3];
    const float* W1 = (const float*)d_in[4];
    const float* b1 = (const float*)d_in[5];
    const float* ga = (const float*)d_in[6];
    const float* be = (const float*)d_in[7];
    const float* W2 = (const float*)d_in[8];
    const float* b2 = (const float*)d_in[9];
    const float* Wl = (const float*)d_in[10];
    const float* bl = (const float*)d_in[11];
    const float* Wr = (const float*)d_in[12];
    const float* br = (const float*)d_in[13];
    const float* We = (const float*)d_in[14];
    const float* att = (const float*)d_in[15];
    const float* gb  = (const float*)d_in[16];
    const float* W3 = (const float*)d_in[17];
    const float* b3 = (const float*)d_in[18];
    const float* W4 = (const float*)d_in[19];
    const float* b4 = (const float*)d_in[20];
    float* out = (float*)d_out;

    static uint32_t* w1f = nullptr;
    static uint32_t* w3f = nullptr;
    static uint32_t* w4f = nullptr;
    if (!w1f) {
        cudaGetSymbolAddress((void**)&w1f, g_w1frag);
        cudaGetSymbolAddress((void**)&w3f, g_w3frag);
        cudaGetSymbolAddress((void**)&w4f, g_w4frag);
        cudaFuncSetAttribute(k_mlp_mma, cudaFuncAttributeMaxDynamicSharedMemorySize, SM1_TOTAL);
        cudaFuncSetAttribute(k_out_mma, cudaFuncAttributeMaxDynamicSharedMemorySize, SM2_TOTAL);
    }

    // launch order chosen so ncu (-s 5 -c 1) captures k_edge at index 5
    k_detect<<<1, 256>>>((const unsigned*)mask);                       // 0
    k_initcompact<<<(NN * HC + 255) / 256, 256>>>(mask);               // 1
    k_prep_all<<<288, 256>>>(W1, W3, W4, w1f, w3f, w4f);               // 2
    k_mlp_mma<<<(NN + 127) / 128, 256, SM1_TOTAL>>>(signal, W2, b1, ga, be, b2,
                                                    Wl, bl, Wr, br);   // 3
    k_fill<<<120, 256>>>(b1, ga, be, W2, b2, Wl, bl, Wr, br);          // 4
    k_edge<<<(EE + 255) / 256, 256>>>(ei, ew, We, att);                // 5 <- profiled
    k_out_mma<<<(NN + 127) / 128, 256, SM2_TOTAL>>>(gb, b3, b4, out);  // 6
}

// round 12
// speedup vs baseline: 1.4651x; 1.4651x over previous
#include <cuda_runtime.h>
#include <cuda_bf16.h>
#include <math_constants.h>
#include <cstdint>

#define NN      100000
#define EE      3200000
#define CYD     128
#define H1      512
#define FD      10
#define HC      20
#define H2      512

// ---------------- device scratch ----------------
__device__ float    g_xl[NN * HC];
__device__ float    g_xr[NN * HC];
__device__ float    g_den[NN * 2];
__device__ float    g_num[NN * HC];
__device__ int      g_mask_mode;
__device__ int      g_nu, g_nm;
__device__ int      g_perm[NN];       // unmasked node ids (any order)
__device__ int      g_mlist[NN];      // masked node ids
// fragment-packed weights: per (n8, ks, lane): {b0_hi, b1_hi, b0_lo, b1_lo}
__device__ uint32_t g_w1frag[(H1 / 8) * (CYD / 16) * 32 * 4];
__device__ uint32_t g_w3frag[(H2 / 8) * (32 / 16) * 32 * 4];
__device__ uint32_t g_w4frag[(CYD / 8) * (H2 / 16) * 32 * 4];

// ---------------- helpers ----------------
__device__ __forceinline__ unsigned long long pack2(float a, float b) {
    unsigned long long r;
    asm("mov.b64 %0, {%1, %2};" : "=l"(r) : "f"(a), "f"(b));
    return r;
}
__device__ __forceinline__ float2 unpack2(unsigned long long v) {
    float2 r;
    asm("mov.b64 {%0, %1}, %2;" : "=f"(r.x), "=f"(r.y) : "l"(v));
    return r;
}
__device__ __forceinline__ void fma2(unsigned long long& acc,
                                     unsigned long long a, unsigned long long b) {
    asm("fma.rn.f32x2 %0, %1, %2, %0;" : "+l"(acc) : "l"(a), "l"(b));
}
__device__ __forceinline__ uint32_t pk_bf2(float a, float b) {
    __nv_bfloat162 h = __floats2bfloat162_rn(a, b);
    return *(uint32_t*)&h;
}
__device__ __forceinline__ void mma_bf16(float* c, const uint32_t* a, uint32_t b0, uint32_t b1) {
    asm volatile("mma.sync.aligned.m16n8k16.row.col.f32.bf16.bf16.f32 "
                 "{%0,%1,%2,%3}, {%4,%5,%6,%7}, {%8,%9}, {%0,%1,%2,%3};"
                 : "+f"(c[0]), "+f"(c[1]), "+f"(c[2]), "+f"(c[3])
                 : "r"(a[0]), "r"(a[1]), "r"(a[2]), "r"(a[3]), "r"(b0), "r"(b1));
}

// ---------------- mask dtype detection ----------------
__global__ void k_detect(const unsigned* __restrict__ mw) {
    __shared__ int notInt, notFloat;
    if (threadIdx.x == 0) { notInt = 0; notFloat = 0; }
    __syncthreads();
    unsigned v = mw[threadIdx.x];
    if (v > 1u)                      atomicOr(&notInt, 1);
    if (v != 0u && v != 0x3f800000u) atomicOr(&notFloat, 1);
    __syncthreads();
    if (threadIdx.x == 0)
        g_mask_mode = notInt ? (notFloat ? 0 : 2) : 1;
}

// ---------------- init ----------------
__global__ void k_init() {
    int i = blockIdx.x * blockDim.x + threadIdx.x;
    if (i == 0) { g_nu = 0; g_nm = 0; }
    if (i < NN * HC) g_num[i] = 0.f;
    if (i < NN * 2) g_den[i] = 0.f;
}

// ---------------- node compaction (order-free) ----------------
__global__ void k_compact(const void* __restrict__ mask) {
    int i = blockIdx.x * blockDim.x + threadIdx.x;
    if (i >= NN) return;
    int mode = g_mask_mode;
    bool mk;
    if (mode == 0)      mk = ((const unsigned char*)mask)[i] != 0;
    else if (mode == 1) mk = ((const int*)mask)[i] != 0;
    else                mk = ((const float*)mask)[i] != 0.f;
    if (!mk) g_perm[atomicAdd(&g_nu, 1)] = i;
    else     g_mlist[atomicAdd(&g_nm, 1)] = i;
}

// ---------------- weight fragment prep ----------------
__global__ void k_prep(const float* __restrict__ W, uint32_t* __restrict__ frag,
                       int Kreal, int Kpad, int Nn)
{
    int i = blockIdx.x * blockDim.x + threadIdx.x;
    int kp2 = Kpad >> 1;
    if (i >= Nn * kp2) return;
    int n = i / kp2, k = (i % kp2) * 2;
    float w0 = (k     < Kreal) ? W[(size_t)k * Nn + n]       : 0.f;
    float w1 = (k + 1 < Kreal) ? W[(size_t)(k + 1) * Nn + n] : 0.f;
    float h0f = __bfloat162float(__float2bfloat16(w0));
    float h1f = __bfloat162float(__float2bfloat16(w1));
    uint32_t whi = pk_bf2(h0f, h1f);
    uint32_t wlo = pk_bf2(w0 - h0f, w1 - h1f);
    int n8 = n >> 3, ks = k >> 4;
    int lane = ((n & 7) << 2) | ((k & 7) >> 1);
    int b01 = (k >> 3) & 1;
    int base = ((n8 * (Kpad >> 4) + ks) * 32 + lane) * 4;
    frag[base + b01]     = whi;
    frag[base + 2 + b01] = wlo;
}

// ---------------- masked-node constant fill: xl/xr for x=0 rows ----------------
__global__ void __launch_bounds__(256)
k_fill(const float* __restrict__ b1, const float* __restrict__ gamma,
       const float* __restrict__ beta, const float* __restrict__ W2,
       const float* __restrict__ b2,
       const float* __restrict__ Wl, const float* __restrict__ bl,
       const float* __restrict__ Wr, const float* __restrict__ br)
{
    __shared__ float sh[H1];
    __shared__ float sx2[FD];
    __shared__ __align__(16) float sout[2 * HC];
    const int t = threadIdx.x;
    const float inv = rsqrtf(1.f + 1e-5f);
    for (int h = t; h < H1; h += 256)
        sh[h] = fmaxf(b1[h] * gamma[h] * inv + beta[h], 0.f);
    __syncthreads();
    if (t < FD) {
        float a = b2[t];
        for (int h = 0; h < H1; h++) a += sh[h] * W2[h * FD + t];
        sx2[t] = a;
    }
    __syncthreads();
    if (t < 2 * HC) {
        int j = t % HC;
        bool left = t < HC;
        const float* W = left ? Wl : Wr;
        float a = left ? bl[j] : br[j];
        #pragma unroll
        for (int k = 0; k < FD; k++) a += sx2[k] * W[k * HC + j];
        sout[t] = a;
    }
    __syncthreads();
    const int nm = g_nm;
    for (int i = blockIdx.x * 256 + t; i < nm; i += gridDim.x * 256) {
        int node = g_mlist[i];
        float4* pl = (float4*)&g_xl[(size_t)node * HC];
        float4* pr = (float4*)&g_xr[(size_t)node * HC];
        #pragma unroll
        for (int q = 0; q < 5; q++) {
            pl[q] = *(float4*)&sout[q * 4];
            pr[q] = *(float4*)&sout[HC + q * 4];
        }
    }
}

// =====================================================================
// kernel A: compact rows -> GEMM1(mma bf16 3-pass) -> BN -> ReLU
//           -> GEMM2 -> fused xl/xr epilogue
// =====================================================================
#define A_STRIDE 136
#define OFF_AHI  0
#define OFF_ALO  34816
#define OFF_HSF  69632
#define OFF_W2T  135168
#define OFF_B1   155648
#define OFF_SC   157696
#define OFF_BE   159744
#define OFF_WLR  161792            // Wl[200] Wr[200] bl[20] br[20] = 1760B
#define SM1_TOTAL 163584

__global__ void __launch_bounds__(256, 1)
k_mlp_mma(const float* __restrict__ signal,
          const float* __restrict__ W2, const float* __restrict__ b1,
          const float* __restrict__ gamma, const float* __restrict__ beta,
          const float* __restrict__ b2,
          const float* __restrict__ Wl, const float* __restrict__ bl,
          const float* __restrict__ Wr, const float* __restrict__ br)
{
    extern __shared__ char smem[];
    const int nu = g_nu;
    const int row0 = blockIdx.x * 128;
    if (row0 >= nu) return;

    __nv_bfloat16* Ahi = (__nv_bfloat16*)(smem + OFF_AHI);
    __nv_bfloat16* Alo = (__nv_bfloat16*)(smem + OFF_ALO);
    float2* hsf2 = (float2*)(smem + OFF_HSF);
    float*  x2s  = (float*)(smem + OFF_HSF);          // reused after GEMM2
    float*  w2t  = (float*)(smem + OFF_W2T);
    float*  sb1  = (float*)(smem + OFF_B1);
    float*  ssc  = (float*)(smem + OFF_SC);
    float*  sbe  = (float*)(smem + OFF_BE);
    float*  sWl  = (float*)(smem + OFF_WLR);
    float*  sWr  = sWl + 200;
    float*  sbl  = sWr + 200;
    float*  sbr  = sbl + 20;

    const int tid = threadIdx.x;
    const int lane = tid & 31;
    const int wid  = tid >> 5;
    const int wm = wid & 3, wn = wid >> 2;
    const int g  = lane >> 2, q4 = lane & 3;

    const float inv = rsqrtf(1.f + 1e-5f);
    for (int i = tid; i < H1; i += 256) {
        sb1[i] = b1[i];
        ssc[i] = gamma[i] * inv;
        sbe[i] = beta[i];
    }
    for (int i = tid; i < H1 * FD; i += 256) {
        int c = i / H1, k = i % H1;
        w2t[c * H1 + k] = W2[(size_t)k * FD + c];
    }
    if (tid < 200) { sWl[tid] = Wl[tid]; sWr[tid] = Wr[tid]; }
    else if (tid < 220) sbl[tid - 200] = bl[tid - 200];
    else if (tid < 240) sbr[tid - 220] = br[tid - 220];

    // A: compacted rows -> smem bf16 hi/lo
    {
        const int r = tid >> 1, ch = tid & 1;
        const int idx = row0 + r;
        const bool ok = (idx < nu);
        const int n = ok ? g_perm[idx] : 0;
        const float4* xp = (const float4*)&signal[(size_t)n * CYD + ch * 64];
        #pragma unroll
        for (int qq = 0; qq < 8; qq++) {
            float4 v0 = ok ? xp[2 * qq]     : make_float4(0, 0, 0, 0);
            float4 v1 = ok ? xp[2 * qq + 1] : make_float4(0, 0, 0, 0);
            float f[8] = { v0.x, v0.y, v0.z, v0.w, v1.x, v1.y, v1.z, v1.w };
            float fh[8];
            #pragma unroll
            for (int u = 0; u < 8; u++) fh[u] = __bfloat162float(__float2bfloat16(f[u]));
            uint4 hi = make_uint4(pk_bf2(fh[0], fh[1]), pk_bf2(fh[2], fh[3]),
                                  pk_bf2(fh[4], fh[5]), pk_bf2(fh[6], fh[7]));
            uint4 lo = make_uint4(pk_bf2(f[0] - fh[0], f[1] - fh[1]), pk_bf2(f[2] - fh[2], f[3] - fh[3]),
                                  pk_bf2(f[4] - fh[4], f[5] - fh[5]), pk_bf2(f[6] - fh[6], f[7] - fh[7]));
            int eoff = r * A_STRIDE + ch * 64 + qq * 8;
            *(uint4*)&Ahi[eoff] = hi;
            *(uint4*)&Alo[eoff] = lo;
        }
    }
    __syncthreads();

    unsigned long long acc2[5];
    #pragma unroll
    for (int j = 0; j < 5; j++) acc2[j] = 0ull;
    const int r2 = tid & 127, grp = tid >> 7;

    for (int nt = 0; nt < 4; nt++) {
        float acc[2][8][4];
        #pragma unroll
        for (int mt = 0; mt < 2; mt++)
            #pragma unroll
            for (int j = 0; j < 8; j++)
                #pragma unroll
                for (int c = 0; c < 4; c++) acc[mt][j][c] = 0.f;

        #pragma unroll
        for (int ks = 0; ks < 8; ks++) {
            const int k0 = ks * 16 + q4 * 2;
            uint32_t ah[2][4], al[2][4];
            #pragma unroll
            for (int mt = 0; mt < 2; mt++) {
                int ra = wm * 32 + mt * 16 + g;
                ah[mt][0] = *(const uint32_t*)&Ahi[ra * A_STRIDE + k0];
                ah[mt][1] = *(const uint32_t*)&Ahi[(ra + 8) * A_STRIDE + k0];
                ah[mt][2] = *(const uint32_t*)&Ahi[ra * A_STRIDE + k0 + 8];
                ah[mt][3] = *(const uint32_t*)&Ahi[(ra + 8) * A_STRIDE + k0 + 8];
                al[mt][0] = *(const uint32_t*)&Alo[ra * A_STRIDE + k0];
                al[mt][1] = *(const uint32_t*)&Alo[(ra + 8) * A_STRIDE + k0];
                al[mt][2] = *(const uint32_t*)&Alo[ra * A_STRIDE + k0 + 8];
                al[mt][3] = *(const uint32_t*)&Alo[(ra + 8) * A_STRIDE + k0 + 8];
            }
            #pragma unroll
            for (int j = 0; j < 8; j++) {
                int n8 = nt * 16 + wn * 8 + j;
                const uint4 bv = *(const uint4*)&g_w1frag[((n8 * 8 + ks) * 32 + lane) * 4];
                #pragma unroll
                for (int mt = 0; mt < 2; mt++) {
                    mma_bf16(acc[mt][j], ah[mt], bv.x, bv.y);
                    mma_bf16(acc[mt][j], ah[mt], bv.z, bv.w);
                    mma_bf16(acc[mt][j], al[mt], bv.x, bv.y);
                }
            }
        }

        #pragma unroll
        for (int j = 0; j < 8; j++) {
            int hcol = nt * 128 + wn * 64 + j * 8 + q4 * 2;
            float s0 = ssc[hcol], s1 = ssc[hcol + 1];
            float bi0 = sb1[hcol], bi1 = sb1[hcol + 1];
            float be0 = sbe[hcol], be1 = sbe[hcol + 1];
            int cp = wn * 32 + j * 4 + q4;
            #pragma unroll
            for (int mt = 0; mt < 2; mt++) {
                int ra = wm * 32 + mt * 16 + g;
                float v0 = fmaxf((acc[mt][j][0] + bi0) * s0 + be0, 0.f);
                float v1 = fmaxf((acc[mt][j][1] + bi1) * s1 + be1, 0.f);
                float v2 = fmaxf((acc[mt][j][2] + bi0) * s0 + be0, 0.f);
                float v3 = fmaxf((acc[mt][j][3] + bi1) * s1 + be1, 0.f);
                hsf2[cp * 128 + ra]     = make_float2(v0, v1);
                hsf2[cp * 128 + ra + 8] = make_float2(v2, v3);
            }
        }
        __syncthreads();

        {
            #pragma unroll 8
            for (int cp = 0; cp < 64; cp++) {
                float2 h = hsf2[cp * 128 + r2];
                unsigned long long hp = pack2(h.x, h.y);
                #pragma unroll
                for (int j = 0; j < 5; j++) {
                    const float2 w = *(const float2*)&w2t[(grp * 5 + j) * H1 + nt * 128 + cp * 2];
                    fma2(acc2[j], hp, pack2(w.x, w.y));
                }
            }
        }
        __syncthreads();
    }

    // x2 -> smem (stride 13 = conflict-free)
    #pragma unroll
    for (int j = 0; j < 5; j++) {
        float2 u = unpack2(acc2[j]);
        x2s[r2 * 13 + grp * 5 + j] = u.x + u.y + b2[grp * 5 + j];
    }
    __syncthreads();

    // fused xl/xr: grp 0 -> xl, grp 1 -> xr
    {
        const int idx = row0 + r2;
        if (idx < nu) {
            const int node = g_perm[idx];
            float x10[FD];
            #pragma unroll
            for (int k = 0; k < FD; k++) x10[k] = x2s[r2 * 13 + k];
            const float* W  = grp ? sWr : sWl;
            const float* bb = grp ? sbr : sbl;
            float o[HC];
            #pragma unroll
            for (int j = 0; j < HC; j++) {
                float a = bb[j];
                #pragma unroll
                for (int k = 0; k < FD; k++) a += x10[k] * W[k * HC + j];
                o[j] = a;
            }
            float* dst = grp ? &g_xr[(size_t)node * HC] : &g_xl[(size_t)node * HC];
            #pragma unroll
            for (int q = 0; q < 5; q++)
                *(float4*)&dst[q * 4] = make_float4(o[q*4], o[q*4+1], o[q*4+2], o[q*4+3]);
        }
    }
}

// ---------------- fused edge pass: alpha -> exp -> scatter num/den ----------------
__global__ void k_edge(const int* __restrict__ ei, const float* __restrict__ ew,
                       const float* __restrict__ We, const float* __restrict__ att)
{
    int e = blockIdx.x * blockDim.x + threadIdx.x;
    if (e >= EE) return;
    int src = ei[e], dst = ei[EE + e];
    float w = ew[e];
    const float4* xl4 = (const float4*)&g_xl[src * HC];
    const float4* xr4 = (const float4*)&g_xr[dst * HC];
    float xlv[HC];
    float a0 = 0.f, a1 = 0.f;
    #pragma unroll
    for (int q = 0; q < 5; q++) {
        float4 l = xl4[q], r = xr4[q];
        xlv[q * 4 + 0] = l.x; xlv[q * 4 + 1] = l.y;
        xlv[q * 4 + 2] = l.z; xlv[q * 4 + 3] = l.w;
        float vv[4] = { l.x + r.x, l.y + r.y, l.z + r.z, l.w + r.w };
        #pragma unroll
        for (int u = 0; u < 4; u++) {
            int j = q * 4 + u;
            float v = vv[u] + w * We[j];
            v = v > 0.f ? v : 0.2f * v;
            if (j < 10) a0 += v * att[j];
            else        a1 += v * att[j];
        }
    }
    float ex0 = __expf(a0), ex1 = __expf(a1);
    asm volatile("red.global.add.v2.f32 [%0], {%1,%2};"
                 :: "l"(&g_den[dst * 2]), "f"(ex0), "f"(ex1) : "memory");
    float* np = &g_num[dst * HC];
    #pragma unroll
    for (int q = 0; q < 5; q++) {
        float sx = (q * 4 + 0 < 10) ? ex0 : ex1;
        float sy = (q * 4 + 1 < 10) ? ex0 : ex1;
        float sz = (q * 4 + 2 < 10) ? ex0 : ex1;
        float sw = (q * 4 + 3 < 10) ? ex0 : ex1;
        float4 v = make_float4(xlv[q * 4] * sx, xlv[q * 4 + 1] * sy,
                               xlv[q * 4 + 2] * sz, xlv[q * 4 + 3] * sw);
        asm volatile("red.global.add.v4.f32 [%0], {%1,%2,%3,%4};"
                     :: "l"(np + q * 4), "f"(v.x), "f"(v.y), "f"(v.z), "f"(v.w)
                     : "memory");
    }
}

// =====================================================================
// kernel D: normalize -> +gat_bias -> GEMM3(mma) -> GEMM4(mma) -> out
// =====================================================================
#define A3_STRIDE 40
#define H_STRIDE  136
#define OFF_A3H   0
#define OFF_A3L   10240
#define OFF_HH    20480
#define OFF_HL    55296
#define SM2_TOTAL 90112

__global__ void __launch_bounds__(256, 1)
k_out_mma(const float* __restrict__ gat_bias,
          const float* __restrict__ b3, const float* __restrict__ b4,
          float* __restrict__ out)
{
    extern __shared__ char smem[];
    __nv_bfloat16* A3h = (__nv_bfloat16*)(smem + OFF_A3H);
    __nv_bfloat16* A3l = (__nv_bfloat16*)(smem + OFF_A3L);
    __nv_bfloat16* Hh  = (__nv_bfloat16*)(smem + OFF_HH);
    __nv_bfloat16* Hl  = (__nv_bfloat16*)(smem + OFF_HL);

    const int tid = threadIdx.x;
    const int lane = tid & 31;
    const int wid  = tid >> 5;
    const int wm = wid & 3, wn = wid >> 2;
    const int g = lane >> 2, q4 = lane & 3;
    const int row0 = blockIdx.x * 128;

    for (int i = tid; i < 128 * 32; i += 256) {
        int r = i >> 5, c = i & 31;
        A3h[r * A3_STRIDE + c] = __float2bfloat16(0.f);
        A3l[r * A3_STRIDE + c] = __float2bfloat16(0.f);
    }
    __syncthreads();
    for (int i = tid; i < 128 * HC; i += 256) {
        int r = i / HC, c = i % HC;
        int n = row0 + r;
        float v = 0.f;
        if (n < NN)
            v = g_num[(size_t)n * HC + c] / (g_den[n * 2 + c / 10] + 1e-16f) + gat_bias[c];
        __nv_bfloat16 h = __float2bfloat16(v);
        A3h[r * A3_STRIDE + c] = h;
        A3l[r * A3_STRIDE + c] = __float2bfloat16(v - __bfloat162float(h));
    }
    __syncthreads();

    float2 bw[8];
    #pragma unroll
    for (int j = 0; j < 8; j++)
        bw[j] = *(const float2*)&b4[wn * 64 + j * 8 + q4 * 2];

    float acc4[2][8][4];
    #pragma unroll
    for (int mt = 0; mt < 2; mt++)
        #pragma unroll
        for (int j = 0; j < 8; j++)
            #pragma unroll
            for (int c = 0; c < 4; c++) acc4[mt][j][c] = 0.f;

    for (int nt = 0; nt < 4; nt++) {
        float acc3[2][8][4];
        #pragma unroll
        for (int mt = 0; mt < 2; mt++)
            #pragma unroll
            for (int j = 0; j < 8; j++)
                #pragma unroll
                for (int c = 0; c < 4; c++) acc3[mt][j][c] = 0.f;

        #pragma unroll
        for (int ks = 0; ks < 2; ks++) {
            const int k0 = ks * 16 + q4 * 2;
            uint32_t ah[2][4], al[2][4];
            #pragma unroll
            for (int mt = 0; mt < 2; mt++) {
                int ra = wm * 32 + mt * 16 + g;
                ah[mt][0] = *(const uint32_t*)&A3h[ra * A3_STRIDE + k0];
                ah[mt][1] = *(const uint32_t*)&A3h[(ra + 8) * A3_STRIDE + k0];
                ah[mt][2] = *(const uint32_t*)&A3h[ra * A3_STRIDE + k0 + 8];
                ah[mt][3] = *(const uint32_t*)&A3h[(ra + 8) * A3_STRIDE + k0 + 8];
                al[mt][0] = *(const uint32_t*)&A3l[ra * A3_STRIDE + k0];
                al[mt][1] = *(const uint32_t*)&A3l[(ra + 8) * A3_STRIDE + k0];
                al[mt][2] = *(const uint32_t*)&A3l[ra * A3_STRIDE + k0 + 8];
                al[mt][3] = *(const uint32_t*)&A3l[(ra + 8) * A3_STRIDE + k0 + 8];
            }
            #pragma unroll
            for (int j = 0; j < 8; j++) {
                int n8 = nt * 16 + wn * 8 + j;
                const uint4 bv = *(const uint4*)&g_w3frag[((n8 * 2 + ks) * 32 + lane) * 4];
                #pragma unroll
                for (int mt = 0; mt < 2; mt++) {
                    mma_bf16(acc3[mt][j], ah[mt], bv.x, bv.y);
                    mma_bf16(acc3[mt][j], ah[mt], bv.z, bv.w);
                    mma_bf16(acc3[mt][j], al[mt], bv.x, bv.y);
                }
            }
        }

        #pragma unroll
        for (int j = 0; j < 8; j++) {
            int hcol = nt * 128 + wn * 64 + j * 8 + q4 * 2;
            float2 bb = *(const float2*)&b3[hcol];
            int cl = wn * 64 + j * 8 + q4 * 2;
            #pragma unroll
            for (int mt = 0; mt < 2; mt++) {
                int ra = wm * 32 + mt * 16 + g;
                float v0 = acc3[mt][j][0] + bb.x;
                float v1 = acc3[mt][j][1] + bb.y;
                float v2 = acc3[mt][j][2] + bb.x;
                float v3 = acc3[mt][j][3] + bb.y;
                float h0 = __bfloat162float(__float2bfloat16(v0));
                float h1 = __bfloat162float(__float2bfloat16(v1));
                float h2 = __bfloat162float(__float2bfloat16(v2));
                float h3 = __bfloat162float(__float2bfloat16(v3));
                *(uint32_t*)&Hh[ra * H_STRIDE + cl]       = pk_bf2(h0, h1);
                *(uint32_t*)&Hh[(ra + 8) * H_STRIDE + cl] = pk_bf2(h2, h3);
                *(uint32_t*)&Hl[ra * H_STRIDE + cl]       = pk_bf2(v0 - h0, v1 - h1);
                *(uint32_t*)&Hl[(ra + 8) * H_STRIDE + cl] = pk_bf2(v2 - h2, v3 - h3);
            }
        }
        __syncthreads();

        #pragma unroll
        for (int ks = 0; ks < 8; ks++) {
            const int k0 = ks * 16 + q4 * 2;
            uint32_t ah[2][4], al[2][4];
            #pragma unroll
            for (int mt = 0; mt < 2; mt++) {
                int ra = wm * 32 + mt * 16 + g;
                ah[mt][0] = *(const uint32_t*)&Hh[ra * H_STRIDE + k0];
                ah[mt][1] = *(const uint32_t*)&Hh[(ra + 8) * H_STRIDE + k0];
                ah[mt][2] = *(const uint32_t*)&Hh[ra * H_STRIDE + k0 + 8];
                ah[mt][3] = *(const uint32_t*)&Hh[(ra + 8) * H_STRIDE + k0 + 8];
                al[mt][0] = *(const uint32_t*)&Hl[ra * H_STRIDE + k0];
                al[mt][1] = *(const uint32_t*)&Hl[(ra + 8) * H_STRIDE + k0];
                al[mt][2] = *(const uint32_t*)&Hl[ra * H_STRIDE + k0 + 8];
                al[mt][3] = *(const uint32_t*)&Hl[(ra + 8) * H_STRIDE + k0 + 8];
            }
            #pragma unroll
            for (int j = 0; j < 8; j++) {
                int n8 = wn * 8 + j;
                int ksg = nt * 8 + ks;
                const uint4 bv = *(const uint4*)&g_w4frag[((n8 * 32 + ksg) * 32 + lane) * 4];
                #pragma unroll
                for (int mt = 0; mt < 2; mt++) {
                    mma_bf16(acc4[mt][j], ah[mt], bv.x, bv.y);
                    mma_bf16(acc4[mt][j], ah[mt], bv.z, bv.w);
                    mma_bf16(acc4[mt][j], al[mt], bv.x, bv.y);
                }
            }
        }
        __syncthreads();
    }

    #pragma unroll
    for (int j = 0; j < 8; j++) {
        int col = wn * 64 + j * 8 + q4 * 2;
        #pragma unroll
        for (int mt = 0; mt < 2; mt++) {
            int ra = row0 + wm * 32 + mt * 16 + g;
            if (ra < NN)
                *(float2*)&out[(size_t)ra * CYD + col] =
                    make_float2(acc4[mt][j][0] + bw[j].x, acc4[mt][j][1] + bw[j].y);
            if (ra + 8 < NN)
                *(float2*)&out[(size_t)(ra + 8) * CYD + col] =
                    make_float2(acc4[mt][j][2] + bw[j].x, acc4[mt][j][3] + bw[j].y);
        }
    }
}

// ---------------- launch ----------------
extern "C" void kernel_launch(void* const* d_in, const int* in_sizes, int n_in,
                              void* d_out, int out_size)
{
    const float* signal = (const float*)d_in[0];
    const int*   ei     = (const int*)  d_in[1];
    const float* ew     = (const float*)d_in[2];
    const void*  mask   =               d_in[3];
    const float* W1 = (const float*)d_in[4];
    const float* b1 = (const float*)d_in[5];
    const float* ga = (const float*)d_in[6];
    const float* be = (const float*)d_in[7];
    const float* W2 = (const float*)d_in[8];
    const float* b2 = (const float*)d_in[9];
    const float* Wl = (const float*)d_in[10];
    const float* bl = (const float*)d_in[11];
    const float* Wr = (const float*)d_in[12];
    const float* br = (const float*)d_in[13];
    const float* We = (const float*)d_in[14];
    const float* att = (const float*)d_in[15];
    const float* gb  = (const float*)d_in[16];
    const float* W3 = (const float*)d_in[17];
    const float* b3 = (const float*)d_in[18];
    const float* W4 = (const float*)d_in[19];
    const float* b4 = (const float*)d_in[20];
    float* out = (float*)d_out;

    static uint32_t* w1f = nullptr;
    static uint32_t* w3f = nullptr;
    static uint32_t* w4f = nullptr;
    if (!w1f) {
        cudaGetSymbolAddress((void**)&w1f, g_w1frag);
        cudaGetSymbolAddress((void**)&w3f, g_w3frag);
        cudaGetSymbolAddress((void**)&w4f, g_w4frag);
        cudaFuncSetAttribute(k_mlp_mma, cudaFuncAttributeMaxDynamicSharedMemorySize, SM1_TOTAL);
        cudaFuncSetAttribute(k_out_mma, cudaFuncAttributeMaxDynamicSharedMemorySize, SM2_TOTAL);
    }

    // R10 kernels, reordered only: independent launches moved so that
    // ncu (-s 5 -c 1) profiles k_mlp_mma (launch index 5).
    // Deps: fill<-{compact}; mlp<-{compact,prepW1}; edge<-{mlp,fill,init};
    //       out<-{edge,prepW3,prepW4}
    k_detect<<<1, 256>>>((const unsigned*)mask);                          // 0
    k_init<<<(NN * HC + 255) / 256, 256>>>();                             // 1
    k_compact<<<(NN + 255) / 256, 256>>>(mask);                           // 2
    k_prep<<<(H1 * CYD / 2 + 255) / 256, 256>>>(W1, w1f, CYD, CYD, H1);   // 3
    k_fill<<<120, 256>>>(b1, ga, be, W2, b2, Wl, bl, Wr, br);             // 4
    k_mlp_mma<<<(NN + 127) / 128, 256, SM1_TOTAL>>>(signal, W2, b1, ga, be, b2,
                                                    Wl, bl, Wr, br);      // 5 <- profiled
    k_edge<<<(EE + 255) / 256, 256>>>(ei, ew, We, att);                   // 6
    k_prep<<<(H2 * 32 / 2 + 255) / 256, 256>>>(W3, w3f, HC, 32, H2);      // 7
    k_prep<<<(CYD * H2 / 2 + 255) / 256, 256>>>(W4, w4f, H2, H2, CYD);    // 8
    k_out_mma<<<(NN + 127) / 128, 256, SM2_TOTAL>>>(gb, b3, b4, out);     // 9
}

// round 14
// speedup vs baseline: 1.4717x; 1.0045x over previous
#include <cuda_runtime.h>
#include <cuda_bf16.h>
#include <math_constants.h>
#include <cstdint>

#define NN      100000
#define EE      3200000
#define CYD     128
#define H1      512
#define FD      10
#define HC      20
#define H2      512

// ---------------- device scratch ----------------
__device__ float    g_xl[NN * HC];
__device__ float    g_xr[NN * HC];
__device__ float    g_den[NN * 2];
__device__ float    g_num[NN * HC];
__device__ int      g_mask_mode;
__device__ int      g_nu, g_nm;
__device__ int      g_perm[NN];       // unmasked node ids (any order)
__device__ int      g_mlist[NN];      // masked node ids
// fragment-packed weights: per (n8, ks, lane): {b0_hi, b1_hi, b0_lo, b1_lo}
__device__ uint32_t g_w1frag[(H1 / 8) * (CYD / 16) * 32 * 4];
__device__ uint32_t g_w3frag[(H2 / 8) * (32 / 16) * 32 * 4];
__device__ uint32_t g_w4frag[(CYD / 8) * (H2 / 16) * 32 * 4];

// ---------------- helpers ----------------
__device__ __forceinline__ unsigned long long pack2(float a, float b) {
    unsigned long long r;
    asm("mov.b64 %0, {%1, %2};" : "=l"(r) : "f"(a), "f"(b));
    return r;
}
__device__ __forceinline__ float2 unpack2(unsigned long long v) {
    float2 r;
    asm("mov.b64 {%0, %1}, %2;" : "=f"(r.x), "=f"(r.y) : "l"(v));
    return r;
}
__device__ __forceinline__ void fma2(unsigned long long& acc,
                                     unsigned long long a, unsigned long long b) {
    asm("fma.rn.f32x2 %0, %1, %2, %0;" : "+l"(acc) : "l"(a), "l"(b));
}
__device__ __forceinline__ uint32_t pk_bf2(float a, float b) {
    __nv_bfloat162 h = __floats2bfloat162_rn(a, b);
    return *(uint32_t*)&h;
}
__device__ __forceinline__ void mma_bf16(float* c, const uint32_t* a, uint32_t b0, uint32_t b1) {
    asm volatile("mma.sync.aligned.m16n8k16.row.col.f32.bf16.bf16.f32 "
                 "{%0,%1,%2,%3}, {%4,%5,%6,%7}, {%8,%9}, {%0,%1,%2,%3};"
                 : "+f"(c[0]), "+f"(c[1]), "+f"(c[2]), "+f"(c[3])
                 : "r"(a[0]), "r"(a[1]), "r"(a[2]), "r"(a[3]), "r"(b0), "r"(b1));
}
// ldmatrix x4: loads a full m16k16 bf16 A-fragment (a0..a3) in ONE instruction.
// frag0=(r0-7,k0-7) frag1=(r8-15,k0-7) frag2=(r0-7,k8-15) frag3=(r8-15,k8-15)
__device__ __forceinline__ void ldsm_x4(uint32_t* r, uint32_t saddr) {
    asm volatile("ldmatrix.sync.aligned.m8n8.x4.shared.b16 {%0,%1,%2,%3}, [%4];"
                 : "=r"(r[0]), "=r"(r[1]), "=r"(r[2]), "=r"(r[3]) : "r"(saddr));
}
__device__ __forceinline__ uint32_t smem_u32(const void* p) {
    return (uint32_t)__cvta_generic_to_shared(p);
}

// ---------------- mask dtype detection ----------------
__global__ void k_detect(const unsigned* __restrict__ mw) {
    __shared__ int notInt, notFloat;
    if (threadIdx.x == 0) { notInt = 0; notFloat = 0; }
    __syncthreads();
    unsigned v = mw[threadIdx.x];
    if (v > 1u)                      atomicOr(&notInt, 1);
    if (v != 0u && v != 0x3f800000u) atomicOr(&notFloat, 1);
    __syncthreads();
    if (threadIdx.x == 0)
        g_mask_mode = notInt ? (notFloat ? 0 : 2) : 1;
}

// ---------------- init ----------------
__global__ void k_init() {
    int i = blockIdx.x * blockDim.x + threadIdx.x;
    if (i == 0) { g_nu = 0; g_nm = 0; }
    if (i < NN * HC) g_num[i] = 0.f;
    if (i < NN * 2) g_den[i] = 0.f;
}

// ---------------- node compaction (order-free) ----------------
__global__ void k_compact(const void* __restrict__ mask) {
    int i = blockIdx.x * blockDim.x + threadIdx.x;
    if (i >= NN) return;
    int mode = g_mask_mode;
    bool mk;
    if (mode == 0)      mk = ((const unsigned char*)mask)[i] != 0;
    else if (mode == 1) mk = ((const int*)mask)[i] != 0;
    else                mk = ((const float*)mask)[i] != 0.f;
    if (!mk) g_perm[atomicAdd(&g_nu, 1)] = i;
    else     g_mlist[atomicAdd(&g_nm, 1)] = i;
}

// ---------------- weight fragment prep ----------------
__global__ void k_prep(const float* __restrict__ W, uint32_t* __restrict__ frag,
                       int Kreal, int Kpad, int Nn)
{
    int i = blockIdx.x * blockDim.x + threadIdx.x;
    int kp2 = Kpad >> 1;
    if (i >= Nn * kp2) return;
    int n = i / kp2, k = (i % kp2) * 2;
    float w0 = (k     < Kreal) ? W[(size_t)k * Nn + n]       : 0.f;
    float w1 = (k + 1 < Kreal) ? W[(size_t)(k + 1) * Nn + n] : 0.f;
    float h0f = __bfloat162float(__float2bfloat16(w0));
    float h1f = __bfloat162float(__float2bfloat16(w1));
    uint32_t whi = pk_bf2(h0f, h1f);
    uint32_t wlo = pk_bf2(w0 - h0f, w1 - h1f);
    int n8 = n >> 3, ks = k >> 4;
    int lane = ((n & 7) << 2) | ((k & 7) >> 1);
    int b01 = (k >> 3) & 1;
    int base = ((n8 * (Kpad >> 4) + ks) * 32 + lane) * 4;
    frag[base + b01]     = whi;
    frag[base + 2 + b01] = wlo;
}

// ---------------- masked-node constant fill: xl/xr for x=0 rows ----------------
__global__ void __launch_bounds__(256)
k_fill(const float* __restrict__ b1, const float* __restrict__ gamma,
       const float* __restrict__ beta, const float* __restrict__ W2,
       const float* __restrict__ b2,
       const float* __restrict__ Wl, const float* __restrict__ bl,
       const float* __restrict__ Wr, const float* __restrict__ br)
{
    __shared__ float sh[H1];
    __shared__ float sx2[FD];
    __shared__ __align__(16) float sout[2 * HC];
    const int t = threadIdx.x;
    const float inv = rsqrtf(1.f + 1e-5f);
    for (int h = t; h < H1; h += 256)
        sh[h] = fmaxf(b1[h] * gamma[h] * inv + beta[h], 0.f);
    __syncthreads();
    if (t < FD) {
        float a = b2[t];
        for (int h = 0; h < H1; h++) a += sh[h] * W2[h * FD + t];
        sx2[t] = a;
    }
    __syncthreads();
    if (t < 2 * HC) {
        int j = t % HC;
        bool left = t < HC;
        const float* W = left ? Wl : Wr;
        float a = left ? bl[j] : br[j];
        #pragma unroll
        for (int k = 0; k < FD; k++) a += sx2[k] * W[k * HC + j];
        sout[t] = a;
    }
    __syncthreads();
    const int nm = g_nm;
    for (int i = blockIdx.x * 256 + t; i < nm; i += gridDim.x * 256) {
        int node = g_mlist[i];
        float4* pl = (float4*)&g_xl[(size_t)node * HC];
        float4* pr = (float4*)&g_xr[(size_t)node * HC];
        #pragma unroll
        for (int q = 0; q < 5; q++) {
            pl[q] = *(float4*)&sout[q * 4];
            pr[q] = *(float4*)&sout[HC + q * 4];
        }
    }
}

// =====================================================================
// kernel A: compact rows -> GEMM1(mma bf16 3-pass, ldmatrix) -> BN -> ReLU
//           -> GEMM2 -> fused xl/xr epilogue
// =====================================================================
#define A_STRIDE 136
#define OFF_AHI  0
#define OFF_ALO  34816
#define OFF_HSF  69632
#define OFF_W2T  135168
#define OFF_B1   155648
#define OFF_SC   157696
#define OFF_BE   159744
#define OFF_WLR  161792            // Wl[200] Wr[200] bl[20] br[20] = 1760B
#define SM1_TOTAL 163584

__global__ void __launch_bounds__(256, 1)
k_mlp_mma(const float* __restrict__ signal,
          const float* __restrict__ W2, const float* __restrict__ b1,
          const float* __restrict__ gamma, const float* __restrict__ beta,
          const float* __restrict__ b2,
          const float* __restrict__ Wl, const float* __restrict__ bl,
          const float* __restrict__ Wr, const float* __restrict__ br)
{
    extern __shared__ char smem[];
    const int nu = g_nu;
    const int row0 = blockIdx.x * 128;
    if (row0 >= nu) return;

    __nv_bfloat16* Ahi = (__nv_bfloat16*)(smem + OFF_AHI);
    __nv_bfloat16* Alo = (__nv_bfloat16*)(smem + OFF_ALO);
    float2* hsf2 = (float2*)(smem + OFF_HSF);
    float*  x2s  = (float*)(smem + OFF_HSF);          // reused after GEMM2
    float*  w2t  = (float*)(smem + OFF_W2T);
    float*  sb1  = (float*)(smem + OFF_B1);
    float*  ssc  = (float*)(smem + OFF_SC);
    float*  sbe  = (float*)(smem + OFF_BE);
    float*  sWl  = (float*)(smem + OFF_WLR);
    float*  sWr  = sWl + 200;
    float*  sbl  = sWr + 200;
    float*  sbr  = sbl + 20;

    const int tid = threadIdx.x;
    const int lane = tid & 31;
    const int wid  = tid >> 5;
    const int wm = wid & 3, wn = wid >> 2;
    const int g  = lane >> 2, q4 = lane & 3;

    const float inv = rsqrtf(1.f + 1e-5f);
    for (int i = tid; i < H1; i += 256) {
        sb1[i] = b1[i];
        ssc[i] = gamma[i] * inv;
        sbe[i] = beta[i];
    }
    for (int i = tid; i < H1 * FD; i += 256) {
        int c = i / H1, k = i % H1;
        w2t[c * H1 + k] = W2[(size_t)k * FD + c];
    }
    if (tid < 200) { sWl[tid] = Wl[tid]; sWr[tid] = Wr[tid]; }
    else if (tid < 220) sbl[tid - 200] = bl[tid - 200];
    else if (tid < 240) sbr[tid - 220] = br[tid - 220];

    // A: compacted rows -> smem bf16 hi/lo
    {
        const int r = tid >> 1, ch = tid & 1;
        const int idx = row0 + r;
        const bool ok = (idx < nu);
        const int n = ok ? g_perm[idx] : 0;
        const float4* xp = (const float4*)&signal[(size_t)n * CYD + ch * 64];
        #pragma unroll
        for (int qq = 0; qq < 8; qq++) {
            float4 v0 = ok ? xp[2 * qq]     : make_float4(0, 0, 0, 0);
            float4 v1 = ok ? xp[2 * qq + 1] : make_float4(0, 0, 0, 0);
            float f[8] = { v0.x, v0.y, v0.z, v0.w, v1.x, v1.y, v1.z, v1.w };
            float fh[8];
            #pragma unroll
            for (int u = 0; u < 8; u++) fh[u] = __bfloat162float(__float2bfloat16(f[u]));
            uint4 hi = make_uint4(pk_bf2(fh[0], fh[1]), pk_bf2(fh[2], fh[3]),
                                  pk_bf2(fh[4], fh[5]), pk_bf2(fh[6], fh[7]));
            uint4 lo = make_uint4(pk_bf2(f[0] - fh[0], f[1] - fh[1]), pk_bf2(f[2] - fh[2], f[3] - fh[3]),
                                  pk_bf2(f[4] - fh[4], f[5] - fh[5]), pk_bf2(f[6] - fh[6], f[7] - fh[7]));
            int eoff = r * A_STRIDE + ch * 64 + qq * 8;
            *(uint4*)&Ahi[eoff] = hi;
            *(uint4*)&Alo[eoff] = lo;
        }
    }
    __syncthreads();

    unsigned long long acc2[5];
    #pragma unroll
    for (int j = 0; j < 5; j++) acc2[j] = 0ull;
    const int r2 = tid & 127, grp = tid >> 7;

    // ldmatrix per-lane byte offsets (row = wm*32 + mt*16 + (lane&15), kblk = (lane>>4)*8)
    const uint32_t ahi_s = smem_u32(Ahi);
    const uint32_t alo_s = smem_u32(Alo);
    const int lrow = lane & 15;
    const int lkb  = (lane >> 4) * 8;
    const uint32_t aoff0 = (uint32_t)(((wm * 32 + 0  + lrow) * A_STRIDE + lkb) * 2);
    const uint32_t aoff1 = (uint32_t)(((wm * 32 + 16 + lrow) * A_STRIDE + lkb) * 2);

    for (int nt = 0; nt < 4; nt++) {
        float acc[2][8][4];
        #pragma unroll
        for (int mt = 0; mt < 2; mt++)
            #pragma unroll
            for (int j = 0; j < 8; j++)
                #pragma unroll
                for (int c = 0; c < 4; c++) acc[mt][j][c] = 0.f;

        #pragma unroll
        for (int ks = 0; ks < 8; ks++) {
            uint32_t ah[2][4], al[2][4];
            ldsm_x4(ah[0], ahi_s + aoff0 + ks * 32);
            ldsm_x4(ah[1], ahi_s + aoff1 + ks * 32);
            ldsm_x4(al[0], alo_s + aoff0 + ks * 32);
            ldsm_x4(al[1], alo_s + aoff1 + ks * 32);
            #pragma unroll
            for (int j = 0; j < 8; j++) {
                int n8 = nt * 16 + wn * 8 + j;
                const uint4 bv = *(const uint4*)&g_w1frag[((n8 * 8 + ks) * 32 + lane) * 4];
                #pragma unroll
                for (int mt = 0; mt < 2; mt++) {
                    mma_bf16(acc[mt][j], ah[mt], bv.x, bv.y);
                    mma_bf16(acc[mt][j], ah[mt], bv.z, bv.w);
                    mma_bf16(acc[mt][j], al[mt], bv.x, bv.y);
                }
            }
        }

        #pragma unroll
        for (int j = 0; j < 8; j++) {
            int hcol = nt * 128 + wn * 64 + j * 8 + q4 * 2;
            float s0 = ssc[hcol], s1 = ssc[hcol + 1];
            float bi0 = sb1[hcol], bi1 = sb1[hcol + 1];
            float be0 = sbe[hcol], be1 = sbe[hcol + 1];
            int cp = wn * 32 + j * 4 + q4;
            #pragma unroll
            for (int mt = 0; mt < 2; mt++) {
                int ra = wm * 32 + mt * 16 + g;
                float v0 = fmaxf((acc[mt][j][0] + bi0) * s0 + be0, 0.f);
                float v1 = fmaxf((acc[mt][j][1] + bi1) * s1 + be1, 0.f);
                float v2 = fmaxf((acc[mt][j][2] + bi0) * s0 + be0, 0.f);
                float v3 = fmaxf((acc[mt][j][3] + bi1) * s1 + be1, 0.f);
                hsf2[cp * 128 + ra]     = make_float2(v0, v1);
                hsf2[cp * 128 + ra + 8] = make_float2(v2, v3);
            }
        }
        __syncthreads();

        {
            #pragma unroll 8
            for (int cp = 0; cp < 64; cp++) {
                float2 h = hsf2[cp * 128 + r2];
                unsigned long long hp = pack2(h.x, h.y);
                #pragma unroll
                for (int j = 0; j < 5; j++) {
                    const float2 w = *(const float2*)&w2t[(grp * 5 + j) * H1 + nt * 128 + cp * 2];
                    fma2(acc2[j], hp, pack2(w.x, w.y));
                }
            }
        }
        __syncthreads();
    }

    // x2 -> smem (stride 13 = conflict-free)
    #pragma unroll
    for (int j = 0; j < 5; j++) {
        float2 u = unpack2(acc2[j]);
        x2s[r2 * 13 + grp * 5 + j] = u.x + u.y + b2[grp * 5 + j];
    }
    __syncthreads();

    // fused xl/xr: grp 0 -> xl, grp 1 -> xr
    {
        const int idx = row0 + r2;
        if (idx < nu) {
            const int node = g_perm[idx];
            float x10[FD];
            #pragma unroll
            for (int k = 0; k < FD; k++) x10[k] = x2s[r2 * 13 + k];
            const float* W  = grp ? sWr : sWl;
            const float* bb = grp ? sbr : sbl;
            float o[HC];
            #pragma unroll
            for (int j = 0; j < HC; j++) {
                float a = bb[j];
                #pragma unroll
                for (int k = 0; k < FD; k++) a += x10[k] * W[k * HC + j];
                o[j] = a;
            }
            float* dst = grp ? &g_xr[(size_t)node * HC] : &g_xl[(size_t)node * HC];
            #pragma unroll
            for (int q = 0; q < 5; q++)
                *(float4*)&dst[q * 4] = make_float4(o[q*4], o[q*4+1], o[q*4+2], o[q*4+3]);
        }
    }
}

// ---------------- fused edge pass: alpha -> exp -> scatter num/den ----------------
__global__ void k_edge(const int* __restrict__ ei, const float* __restrict__ ew,
                       const float* __restrict__ We, const float* __restrict__ att)
{
    int e = blockIdx.x * blockDim.x + threadIdx.x;
    if (e >= EE) return;
    int src = ei[e], dst = ei[EE + e];
    float w = ew[e];
    const float4* xl4 = (const float4*)&g_xl[src * HC];
    const float4* xr4 = (const float4*)&g_xr[dst * HC];
    float xlv[HC];
    float a0 = 0.f, a1 = 0.f;
    #pragma unroll
    for (int q = 0; q < 5; q++) {
        float4 l = xl4[q], r = xr4[q];
        xlv[q * 4 + 0] = l.x; xlv[q * 4 + 1] = l.y;
        xlv[q * 4 + 2] = l.z; xlv[q * 4 + 3] = l.w;
        float vv[4] = { l.x + r.x, l.y + r.y, l.z + r.z, l.w + r.w };
        #pragma unroll
        for (int u = 0; u < 4; u++) {
            int j = q * 4 + u;
            float v = vv[u] + w * We[j];
            v = v > 0.f ? v : 0.2f * v;
            if (j < 10) a0 += v * att[j];
            else        a1 += v * att[j];
        }
    }
    float ex0 = __expf(a0), ex1 = __expf(a1);
    asm volatile("red.global.add.v2.f32 [%0], {%1,%2};"
                 :: "l"(&g_den[dst * 2]), "f"(ex0), "f"(ex1) : "memory");
    float* np = &g_num[dst * HC];
    #pragma unroll
    for (int q = 0; q < 5; q++) {
        float sx = (q * 4 + 0 < 10) ? ex0 : ex1;
        float sy = (q * 4 + 1 < 10) ? ex0 : ex1;
        float sz = (q * 4 + 2 < 10) ? ex0 : ex1;
        float sw = (q * 4 + 3 < 10) ? ex0 : ex1;
        float4 v = make_float4(xlv[q * 4] * sx, xlv[q * 4 + 1] * sy,
                               xlv[q * 4 + 2] * sz, xlv[q * 4 + 3] * sw);
        asm volatile("red.global.add.v4.f32 [%0], {%1,%2,%3,%4};"
                     :: "l"(np + q * 4), "f"(v.x), "f"(v.y), "f"(v.z), "f"(v.w)
                     : "memory");
    }
}

// =====================================================================
// kernel D: normalize -> +gat_bias -> GEMM3(mma, ldmatrix) -> GEMM4(mma, ldmatrix) -> out
// =====================================================================
#define A3_STRIDE 40
#define H_STRIDE  136
#define OFF_A3H   0
#define OFF_A3L   10240
#define OFF_HH    20480
#define OFF_HL    55296
#define SM2_TOTAL 90112

__global__ void __launch_bounds__(256, 1)
k_out_mma(const float* __restrict__ gat_bias,
          const float* __restrict__ b3, const float* __restrict__ b4,
          float* __restrict__ out)
{
    extern __shared__ char smem[];
    __nv_bfloat16* A3h = (__nv_bfloat16*)(smem + OFF_A3H);
    __nv_bfloat16* A3l = (__nv_bfloat16*)(smem + OFF_A3L);
    __nv_bfloat16* Hh  = (__nv_bfloat16*)(smem + OFF_HH);
    __nv_bfloat16* Hl  = (__nv_bfloat16*)(smem + OFF_HL);

    const int tid = threadIdx.x;
    const int lane = tid & 31;
    const int wid  = tid >> 5;
    const int wm = wid & 3, wn = wid >> 2;
    const int g = lane >> 2, q4 = lane & 3;
    const int row0 = blockIdx.x * 128;

    for (int i = tid; i < 128 * 32; i += 256) {
        int r = i >> 5, c = i & 31;
        A3h[r * A3_STRIDE + c] = __float2bfloat16(0.f);
        A3l[r * A3_STRIDE + c] = __float2bfloat16(0.f);
    }
    __syncthreads();
    for (int i = tid; i < 128 * HC; i += 256) {
        int r = i / HC, c = i % HC;
        int n = row0 + r;
        float v = 0.f;
        if (n < NN)
            v = g_num[(size_t)n * HC + c] / (g_den[n * 2 + c / 10] + 1e-16f) + gat_bias[c];
        __nv_bfloat16 h = __float2bfloat16(v);
        A3h[r * A3_STRIDE + c] = h;
        A3l[r * A3_STRIDE + c] = __float2bfloat16(v - __bfloat162float(h));
    }
    __syncthreads();

    float2 bw[8];
    #pragma unroll
    for (int j = 0; j < 8; j++)
        bw[j] = *(const float2*)&b4[wn * 64 + j * 8 + q4 * 2];

    float acc4[2][8][4];
    #pragma unroll
    for (int mt = 0; mt < 2; mt++)
        #pragma unroll
        for (int j = 0; j < 8; j++)
            #pragma unroll
            for (int c = 0; c < 4; c++) acc4[mt][j][c] = 0.f;

    // ldmatrix per-lane offsets
    const uint32_t a3h_s = smem_u32(A3h);
    const uint32_t a3l_s = smem_u32(A3l);
    const uint32_t hh_s  = smem_u32(Hh);
    const uint32_t hl_s  = smem_u32(Hl);
    const int lrow = lane & 15;
    const int lkb  = (lane >> 4) * 8;
    const uint32_t a3off0 = (uint32_t)(((wm * 32 + 0  + lrow) * A3_STRIDE + lkb) * 2);
    const uint32_t a3off1 = (uint32_t)(((wm * 32 + 16 + lrow) * A3_STRIDE + lkb) * 2);
    const uint32_t hoff0  = (uint32_t)(((wm * 32 + 0  + lrow) * H_STRIDE + lkb) * 2);
    const uint32_t hoff1  = (uint32_t)(((wm * 32 + 16 + lrow) * H_STRIDE + lkb) * 2);

    for (int nt = 0; nt < 4; nt++) {
        float acc3[2][8][4];
        #pragma unroll
        for (int mt = 0; mt < 2; mt++)
            #pragma unroll
            for (int j = 0; j < 8; j++)
                #pragma unroll
                for (int c = 0; c < 4; c++) acc3[mt][j][c] = 0.f;

        #pragma unroll
        for (int ks = 0; ks < 2; ks++) {
            uint32_t ah[2][4], al[2][4];
            ldsm_x4(ah[0], a3h_s + a3off0 + ks * 32);
            ldsm_x4(ah[1], a3h_s + a3off1 + ks * 32);
            ldsm_x4(al[0], a3l_s + a3off0 + ks * 32);
            ldsm_x4(al[1], a3l_s + a3off1 + ks * 32);
            #pragma unroll
            for (int j = 0; j < 8; j++) {
                int n8 = nt * 16 + wn * 8 + j;
                const uint4 bv = *(const uint4*)&g_w3frag[((n8 * 2 + ks) * 32 + lane) * 4];
                #pragma unroll
                for (int mt = 0; mt < 2; mt++) {
                    mma_bf16(acc3[mt][j], ah[mt], bv.x, bv.y);
                    mma_bf16(acc3[mt][j], ah[mt], bv.z, bv.w);
                    mma_bf16(acc3[mt][j], al[mt], bv.x, bv.y);
                }
            }
        }

        #pragma unroll
        for (int j = 0; j < 8; j++) {
            int hcol = nt * 128 + wn * 64 + j * 8 + q4 * 2;
            float2 bb = *(const float2*)&b3[hcol];
            int cl = wn * 64 + j * 8 + q4 * 2;
            #pragma unroll
            for (int mt = 0; mt < 2; mt++) {
                int ra = wm * 32 + mt * 16 + g;
                float v0 = acc3[mt][j][0] + bb.x;
                float v1 = acc3[mt][j][1] + bb.y;
                float v2 = acc3[mt][j][2] + bb.x;
                float v3 = acc3[mt][j][3] + bb.y;
                float h0 = __bfloat162float(__float2bfloat16(v0));
                float h1 = __bfloat162float(__float2bfloat16(v1));
                float h2 = __bfloat162float(__float2bfloat16(v2));
                float h3 = __bfloat162float(__float2bfloat16(v3));
                *(uint32_t*)&Hh[ra * H_STRIDE + cl]       = pk_bf2(h0, h1);
                *(uint32_t*)&Hh[(ra + 8) * H_STRIDE + cl] = pk_bf2(h2, h3);
                *(uint32_t*)&Hl[ra * H_STRIDE + cl]       = pk_bf2(v0 - h0, v1 - h1);
                *(uint32_t*)&Hl[(ra + 8) * H_STRIDE + cl] = pk_bf2(v2 - h2, v3 - h3);
            }
        }
        __syncthreads();

        #pragma unroll
        for (int ks = 0; ks < 8; ks++) {
            uint32_t ah[2][4], al[2][4];
            ldsm_x4(ah[0], hh_s + hoff0 + ks * 32);
            ldsm_x4(ah[1], hh_s + hoff1 + ks * 32);
            ldsm_x4(al[0], hl_s + hoff0 + ks * 32);
            ldsm_x4(al[1], hl_s + hoff1 + ks * 32);
            #pragma unroll
            for (int j = 0; j < 8; j++) {
                int n8 = wn * 8 + j;
                int ksg = nt * 8 + ks;
                const uint4 bv = *(const uint4*)&g_w4frag[((n8 * 32 + ksg) * 32 + lane) * 4];
                #pragma unroll
                for (int mt = 0; mt < 2; mt++) {
                    mma_bf16(acc4[mt][j], ah[mt], bv.x, bv.y);
                    mma_bf16(acc4[mt][j], ah[mt], bv.z, bv.w);
                    mma_bf16(acc4[mt][j], al[mt], bv.x, bv.y);
                }
            }
        }
        __syncthreads();
    }

    #pragma unroll
    for (int j = 0; j < 8; j++) {
        int col = wn * 64 + j * 8 + q4 * 2;
        #pragma unroll
        for (int mt = 0; mt < 2; mt++) {
            int ra = row0 + wm * 32 + mt * 16 + g;
            if (ra < NN)
                *(float2*)&out[(size_t)ra * CYD + col] =
                    make_float2(acc4[mt][j][0] + bw[j].x, acc4[mt][j][1] + bw[j].y);
            if (ra + 8 < NN)
                *(float2*)&out[(size_t)(ra + 8) * CYD + col] =
                    make_float2(acc4[mt][j][2] + bw[j].x, acc4[mt][j][3] + bw[j].y);
        }
    }
}

// ---------------- launch ----------------
extern "C" void kernel_launch(void* const* d_in, const int* in_sizes, int n_in,
                              void* d_out, int out_size)
{
    const float* signal = (const float*)d_in[0];
    const int*   ei     = (const int*)  d_in[1];
    const float* ew     = (const float*)d_in[2];
    const void*  mask   =               d_in[3];
    const float* W1 = (const float*)d_in[4];
    const float* b1 = (const float*)d_in[5];
    const float* ga = (const float*)d_in[6];
    const float* be = (const float*)d_in[7];
    const float* W2 = (const float*)d_in[8];
    const float* b2 = (const float*)d_in[9];
    const float* Wl = (const float*)d_in[10];
    const float* bl = (const float*)d_in[11];
    const float* Wr = (const float*)d_in[12];
    const float* br = (const float*)d_in[13];
    const float* We = (const float*)d_in[14];
    const float* att = (const float*)d_in[15];
    const float* gb  = (const float*)d_in[16];
    const float* W3 = (const float*)d_in[17];
    const float* b3 = (const float*)d_in[18];
    const float* W4 = (const float*)d_in[19];
    const float* b4 = (const float*)d_in[20];
    float* out = (float*)d_out;

    static uint32_t* w1f = nullptr;
    static uint32_t* w3f = nullptr;
    static uint32_t* w4f = nullptr;
    if (!w1f) {
        cudaGetSymbolAddress((void**)&w1f, g_w1frag);
        cudaGetSymbolAddress((void**)&w3f, g_w3frag);
        cudaGetSymbolAddress((void**)&w4f, g_w4frag);
        cudaFuncSetAttribute(k_mlp_mma, cudaFuncAttributeMaxDynamicSharedMemorySize, SM1_TOTAL);
        cudaFuncSetAttribute(k_out_mma, cudaFuncAttributeMaxDynamicSharedMemorySize, SM2_TOTAL);
    }

    k_detect<<<1, 256>>>((const unsigned*)mask);                          // 0
    k_init<<<(NN * HC + 255) / 256, 256>>>();                             // 1
    k_compact<<<(NN + 255) / 256, 256>>>(mask);                           // 2
    k_prep<<<(H1 * CYD / 2 + 255) / 256, 256>>>(W1, w1f, CYD, CYD, H1);   // 3
    k_fill<<<120, 256>>>(b1, ga, be, W2, b2, Wl, bl, Wr, br);             // 4
    k_mlp_mma<<<(NN + 127) / 128, 256, SM1_TOTAL>>>(signal, W2, b1, ga, be, b2,
                                                    Wl, bl, Wr, br);      // 5
    k_edge<<<(EE + 255) / 256, 256>>>(ei, ew, We, att);                   // 6
    k_prep<<<(H2 * 32 / 2 + 255) / 256, 256>>>(W3, w3f, HC, 32, H2);      // 7
    k_prep<<<(CYD * H2 / 2 + 255) / 256, 256>>>(W4, w4f, H2, H2, CYD);    // 8
    k_out_mma<<<(NN + 127) / 128, 256, SM2_TOTAL>>>(gb, b3, b4, out);     // 9
}

// round 15
// speedup vs baseline: 1.5545x; 1.0562x over previous
#include <cuda_runtime.h>
#include <cuda_bf16.h>
#include <math_constants.h>
#include <cstdint>

#define NN      100000
#define EE      3200000
#define CYD     128
#define H1      512
#define FD      10
#define HC      20
#define H2      512

// ---------------- device scratch ----------------
__device__ float    g_xl[NN * HC];
__device__ float    g_xr[NN * HC];
__device__ float    g_den[NN * 2];
__device__ float    g_num[NN * HC];
__device__ int      g_mask_mode;
__device__ int      g_nu, g_nm;
__device__ int      g_perm[NN];       // unmasked node ids (any order)
__device__ int      g_mlist[NN];      // masked node ids
// fragment-packed weights: per (n8, ks, lane): {b0_hi, b1_hi, b0_lo, b1_lo}
__device__ uint32_t g_w1frag[(H1 / 8) * (CYD / 16) * 32 * 4];
__device__ uint32_t g_w2frag[(16 / 8) * (H1 / 16) * 32 * 4];   // W2: N pad 10->16, K=512
__device__ uint32_t g_w3frag[(H2 / 8) * (32 / 16) * 32 * 4];
__device__ uint32_t g_w4frag[(CYD / 8) * (H2 / 16) * 32 * 4];

// ---------------- helpers ----------------
__device__ __forceinline__ uint32_t pk_bf2(float a, float b) {
    __nv_bfloat162 h = __floats2bfloat162_rn(a, b);
    return *(uint32_t*)&h;
}
__device__ __forceinline__ void mma_bf16(float* c, const uint32_t* a, uint32_t b0, uint32_t b1) {
    asm volatile("mma.sync.aligned.m16n8k16.row.col.f32.bf16.bf16.f32 "
                 "{%0,%1,%2,%3}, {%4,%5,%6,%7}, {%8,%9}, {%0,%1,%2,%3};"
                 : "+f"(c[0]), "+f"(c[1]), "+f"(c[2]), "+f"(c[3])
                 : "r"(a[0]), "r"(a[1]), "r"(a[2]), "r"(a[3]), "r"(b0), "r"(b1));
}
// ldmatrix x4: loads a full m16k16 bf16 A-fragment (a0..a3) in ONE instruction.
__device__ __forceinline__ void ldsm_x4(uint32_t* r, uint32_t saddr) {
    asm volatile("ldmatrix.sync.aligned.m8n8.x4.shared.b16 {%0,%1,%2,%3}, [%4];"
                 : "=r"(r[0]), "=r"(r[1]), "=r"(r[2]), "=r"(r[3]) : "r"(saddr));
}
__device__ __forceinline__ uint32_t smem_u32(const void* p) {
    return (uint32_t)__cvta_generic_to_shared(p);
}

// ---------------- mask dtype detection ----------------
__global__ void k_detect(const unsigned* __restrict__ mw) {
    __shared__ int notInt, notFloat;
    if (threadIdx.x == 0) { notInt = 0; notFloat = 0; }
    __syncthreads();
    unsigned v = mw[threadIdx.x];
    if (v > 1u)                      atomicOr(&notInt, 1);
    if (v != 0u && v != 0x3f800000u) atomicOr(&notFloat, 1);
    __syncthreads();
    if (threadIdx.x == 0)
        g_mask_mode = notInt ? (notFloat ? 0 : 2) : 1;
}

// ---------------- init ----------------
__global__ void k_init() {
    int i = blockIdx.x * blockDim.x + threadIdx.x;
    if (i == 0) { g_nu = 0; g_nm = 0; }
    if (i < NN * HC) g_num[i] = 0.f;
    if (i < NN * 2) g_den[i] = 0.f;
}

// ---------------- node compaction (order-free) ----------------
__global__ void k_compact(const void* __restrict__ mask) {
    int i = blockIdx.x * blockDim.x + threadIdx.x;
    if (i >= NN) return;
    int mode = g_mask_mode;
    bool mk;
    if (mode == 0)      mk = ((const unsigned char*)mask)[i] != 0;
    else if (mode == 1) mk = ((const int*)mask)[i] != 0;
    else                mk = ((const float*)mask)[i] != 0.f;
    if (!mk) g_perm[atomicAdd(&g_nu, 1)] = i;
    else     g_mlist[atomicAdd(&g_nm, 1)] = i;
}

// ---------------- weight fragment prep ----------------
__global__ void k_prep(const float* __restrict__ W, uint32_t* __restrict__ frag,
                       int Kreal, int Kpad, int Nn)
{
    int i = blockIdx.x * blockDim.x + threadIdx.x;
    int kp2 = Kpad >> 1;
    if (i >= Nn * kp2) return;
    int n = i / kp2, k = (i % kp2) * 2;
    float w0 = (k     < Kreal) ? W[(size_t)k * Nn + n]       : 0.f;
    float w1 = (k + 1 < Kreal) ? W[(size_t)(k + 1) * Nn + n] : 0.f;
    float h0f = __bfloat162float(__float2bfloat16(w0));
    float h1f = __bfloat162float(__float2bfloat16(w1));
    uint32_t whi = pk_bf2(h0f, h1f);
    uint32_t wlo = pk_bf2(w0 - h0f, w1 - h1f);
    int n8 = n >> 3, ks = k >> 4;
    int lane = ((n & 7) << 2) | ((k & 7) >> 1);
    int b01 = (k >> 3) & 1;
    int base = ((n8 * (Kpad >> 4) + ks) * 32 + lane) * 4;
    frag[base + b01]     = whi;
    frag[base + 2 + b01] = wlo;
}

// ---------------- masked-node constant fill: xl/xr for x=0 rows ----------------
__global__ void __launch_bounds__(256)
k_fill(const float* __restrict__ b1, const float* __restrict__ gamma,
       const float* __restrict__ beta, const float* __restrict__ W2,
       const float* __restrict__ b2,
       const float* __restrict__ Wl, const float* __restrict__ bl,
       const float* __restrict__ Wr, const float* __restrict__ br)
{
    __shared__ float sh[H1];
    __shared__ float sx2[FD];
    __shared__ __align__(16) float sout[2 * HC];
    const int t = threadIdx.x;
    const float inv = rsqrtf(1.f + 1e-5f);
    for (int h = t; h < H1; h += 256)
        sh[h] = fmaxf(b1[h] * gamma[h] * inv + beta[h], 0.f);
    __syncthreads();
    if (t < FD) {
        float a = b2[t];
        for (int h = 0; h < H1; h++) a += sh[h] * W2[h * FD + t];
        sx2[t] = a;
    }
    __syncthreads();
    if (t < 2 * HC) {
        int j = t % HC;
        bool left = t < HC;
        const float* W = left ? Wl : Wr;
        float a = left ? bl[j] : br[j];
        #pragma unroll
        for (int k = 0; k < FD; k++) a += sx2[k] * W[k * HC + j];
        sout[t] = a;
    }
    __syncthreads();
    const int nm = g_nm;
    for (int i = blockIdx.x * 256 + t; i < nm; i += gridDim.x * 256) {
        int node = g_mlist[i];
        float4* pl = (float4*)&g_xl[(size_t)node * HC];
        float4* pr = (float4*)&g_xr[(size_t)node * HC];
        #pragma unroll
        for (int q = 0; q < 5; q++) {
            pl[q] = *(float4*)&sout[q * 4];
            pr[q] = *(float4*)&sout[HC + q * 4];
        }
    }
}

// =====================================================================
// kernel A: compact rows -> GEMM1(mma) -> BN -> ReLU -> GEMM2(mma)
//           -> fused xl/xr epilogue
// =====================================================================
#define A_STRIDE 136
#define OFF_AHI  0
#define OFF_ALO  34816
#define OFF_HH   69632
#define OFF_HL   104448
#define OFF_B1   139264
#define OFF_SC   141312
#define OFF_BE   143360
#define OFF_WLR  145408            // Wl[200] Wr[200] bl[20] br[20] = 1760B
#define SM1_TOTAL 147200

__global__ void __launch_bounds__(256, 1)
k_mlp_mma(const float* __restrict__ signal,
          const float* __restrict__ b1,
          const float* __restrict__ gamma, const float* __restrict__ beta,
          const float* __restrict__ b2,
          const float* __restrict__ Wl, const float* __restrict__ bl,
          const float* __restrict__ Wr, const float* __restrict__ br)
{
    extern __shared__ char smem[];
    const int nu = g_nu;
    const int row0 = blockIdx.x * 128;
    if (row0 >= nu) return;

    __nv_bfloat16* Ahi = (__nv_bfloat16*)(smem + OFF_AHI);
    __nv_bfloat16* Alo = (__nv_bfloat16*)(smem + OFF_ALO);
    __nv_bfloat16* Hh  = (__nv_bfloat16*)(smem + OFF_HH);
    __nv_bfloat16* Hl  = (__nv_bfloat16*)(smem + OFF_HL);
    float*  sb1  = (float*)(smem + OFF_B1);
    float*  ssc  = (float*)(smem + OFF_SC);
    float*  sbe  = (float*)(smem + OFF_BE);
    float*  sWl  = (float*)(smem + OFF_WLR);
    float*  sWr  = sWl + 200;
    float*  sbl  = sWr + 200;
    float*  sbr  = sbl + 20;
    float*  part = (float*)(smem + OFF_HH);   // reused AFTER mainloop: [2][128][17]

    const int tid = threadIdx.x;
    const int lane = tid & 31;
    const int wid  = tid >> 5;
    const int wm = wid & 3, wn = wid >> 2;
    const int g  = lane >> 2, q4 = lane & 3;

    const float inv = rsqrtf(1.f + 1e-5f);
    for (int i = tid; i < H1; i += 256) {
        sb1[i] = b1[i];
        ssc[i] = gamma[i] * inv;
        sbe[i] = beta[i];
    }
    if (tid < 200) { sWl[tid] = Wl[tid]; sWr[tid] = Wr[tid]; }
    else if (tid < 220) sbl[tid - 200] = bl[tid - 200];
    else if (tid < 240) sbr[tid - 220] = br[tid - 220];

    // A: compacted rows -> smem bf16 hi/lo
    {
        const int r = tid >> 1, ch = tid & 1;
        const int idx = row0 + r;
        const bool ok = (idx < nu);
        const int n = ok ? g_perm[idx] : 0;
        const float4* xp = (const float4*)&signal[(size_t)n * CYD + ch * 64];
        #pragma unroll
        for (int qq = 0; qq < 8; qq++) {
            float4 v0 = ok ? xp[2 * qq]     : make_float4(0, 0, 0, 0);
            float4 v1 = ok ? xp[2 * qq + 1] : make_float4(0, 0, 0, 0);
            float f[8] = { v0.x, v0.y, v0.z, v0.w, v1.x, v1.y, v1.z, v1.w };
            float fh[8];
            #pragma unroll
            for (int u = 0; u < 8; u++) fh[u] = __bfloat162float(__float2bfloat16(f[u]));
            uint4 hi = make_uint4(pk_bf2(fh[0], fh[1]), pk_bf2(fh[2], fh[3]),
                                  pk_bf2(fh[4], fh[5]), pk_bf2(fh[6], fh[7]));
            uint4 lo = make_uint4(pk_bf2(f[0] - fh[0], f[1] - fh[1]), pk_bf2(f[2] - fh[2], f[3] - fh[3]),
                                  pk_bf2(f[4] - fh[4], f[5] - fh[5]), pk_bf2(f[6] - fh[6], f[7] - fh[7]));
            int eoff = r * A_STRIDE + ch * 64 + qq * 8;
            *(uint4*)&Ahi[eoff] = hi;
            *(uint4*)&Alo[eoff] = lo;
        }
    }
    __syncthreads();

    const int r2 = tid & 127, grp = tid >> 7;

    // ldmatrix per-lane byte offsets
    const uint32_t ahi_s = smem_u32(Ahi);
    const uint32_t alo_s = smem_u32(Alo);
    const uint32_t hh_s  = smem_u32(Hh);
    const uint32_t hl_s  = smem_u32(Hl);
    const int lrow = lane & 15;
    const int lkb  = (lane >> 4) * 8;
    const uint32_t aoff0 = (uint32_t)(((wm * 32 + 0  + lrow) * A_STRIDE + lkb) * 2);
    const uint32_t aoff1 = (uint32_t)(((wm * 32 + 16 + lrow) * A_STRIDE + lkb) * 2);

    // GEMM2 mma accumulators (persist across nt): rows 2 mt x cols 2 n8
    float acc2m[2][2][4];
    #pragma unroll
    for (int mt = 0; mt < 2; mt++)
        #pragma unroll
        for (int j = 0; j < 2; j++)
            #pragma unroll
            for (int c = 0; c < 4; c++) acc2m[mt][j][c] = 0.f;

    for (int nt = 0; nt < 4; nt++) {
        float acc[2][8][4];
        #pragma unroll
        for (int mt = 0; mt < 2; mt++)
            #pragma unroll
            for (int j = 0; j < 8; j++)
                #pragma unroll
                for (int c = 0; c < 4; c++) acc[mt][j][c] = 0.f;

        #pragma unroll
        for (int ks = 0; ks < 8; ks++) {
            uint32_t ah[2][4], al[2][4];
            ldsm_x4(ah[0], ahi_s + aoff0 + ks * 32);
            ldsm_x4(ah[1], ahi_s + aoff1 + ks * 32);
            ldsm_x4(al[0], alo_s + aoff0 + ks * 32);
            ldsm_x4(al[1], alo_s + aoff1 + ks * 32);
            #pragma unroll
            for (int j = 0; j < 8; j++) {
                int n8 = nt * 16 + wn * 8 + j;
                const uint4 bv = *(const uint4*)&g_w1frag[((n8 * 8 + ks) * 32 + lane) * 4];
                #pragma unroll
                for (int mt = 0; mt < 2; mt++) {
                    mma_bf16(acc[mt][j], ah[mt], bv.x, bv.y);
                    mma_bf16(acc[mt][j], ah[mt], bv.z, bv.w);
                    mma_bf16(acc[mt][j], al[mt], bv.x, bv.y);
                }
            }
        }

        // epilogue: BN + ReLU -> split bf16 hi/lo into Hh/Hl (warp-private block)
        #pragma unroll
        for (int j = 0; j < 8; j++) {
            int hcol = nt * 128 + wn * 64 + j * 8 + q4 * 2;
            float s0 = ssc[hcol], s1 = ssc[hcol + 1];
            float bi0 = sb1[hcol], bi1 = sb1[hcol + 1];
            float be0 = sbe[hcol], be1 = sbe[hcol + 1];
            int cl = wn * 64 + j * 8 + q4 * 2;
            #pragma unroll
            for (int mt = 0; mt < 2; mt++) {
                int ra = wm * 32 + mt * 16 + g;
                float v0 = fmaxf((acc[mt][j][0] + bi0) * s0 + be0, 0.f);
                float v1 = fmaxf((acc[mt][j][1] + bi1) * s1 + be1, 0.f);
                float v2 = fmaxf((acc[mt][j][2] + bi0) * s0 + be0, 0.f);
                float v3 = fmaxf((acc[mt][j][3] + bi1) * s1 + be1, 0.f);
                float h0 = __bfloat162float(__float2bfloat16(v0));
                float h1 = __bfloat162float(__float2bfloat16(v1));
                float h2 = __bfloat162float(__float2bfloat16(v2));
                float h3 = __bfloat162float(__float2bfloat16(v3));
                *(uint32_t*)&Hh[ra * A_STRIDE + cl]       = pk_bf2(h0, h1);
                *(uint32_t*)&Hh[(ra + 8) * A_STRIDE + cl] = pk_bf2(h2, h3);
                *(uint32_t*)&Hl[ra * A_STRIDE + cl]       = pk_bf2(v0 - h0, v1 - h1);
                *(uint32_t*)&Hl[(ra + 8) * A_STRIDE + cl] = pk_bf2(v2 - h2, v3 - h3);
            }
        }
        __syncwarp();   // each warp reads only its own Hh/Hl block

        // GEMM2 mma: this warp's k-halves (wn selects 64 of the 128 local cols)
        #pragma unroll
        for (int ks = 0; ks < 4; ks++) {
            const int kg = wn * 4 + ks;                // local k16-step 0..7
            uint32_t ah[2][4], al[2][4];
            const uint32_t ho = (uint32_t)((kg * 16 + lkb) * 2);
            ldsm_x4(ah[0], hh_s + aoff0 - lkb * 2 + ho);
            ldsm_x4(ah[1], hh_s + aoff1 - lkb * 2 + ho);
            ldsm_x4(al[0], hl_s + aoff0 - lkb * 2 + ho);
            ldsm_x4(al[1], hl_s + aoff1 - lkb * 2 + ho);
            const int ksg = nt * 8 + kg;               // global k16-step 0..31
            #pragma unroll
            for (int j = 0; j < 2; j++) {
                const uint4 bv = *(const uint4*)&g_w2frag[((j * 32 + ksg) * 32 + lane) * 4];
                #pragma unroll
                for (int mt = 0; mt < 2; mt++) {
                    mma_bf16(acc2m[mt][j], ah[mt], bv.x, bv.y);
                    mma_bf16(acc2m[mt][j], ah[mt], bv.z, bv.w);
                    mma_bf16(acc2m[mt][j], al[mt], bv.x, bv.y);
                }
            }
        }
        __syncwarp();   // next nt overwrites this warp's Hh/Hl block
    }

    // combine wn partials: part[wn][row][17] (stride 17 = conflict-free)
    __syncthreads();    // all warps done reading Hh before reuse as `part`
    #pragma unroll
    for (int mt = 0; mt < 2; mt++) {
        #pragma unroll
        for (int j = 0; j < 2; j++) {
            int c0 = j * 8 + q4 * 2;
            int ra = wm * 32 + mt * 16 + g;
            part[(wn * 128 + ra) * 17 + c0]           = acc2m[mt][j][0];
            part[(wn * 128 + ra) * 17 + c0 + 1]       = acc2m[mt][j][1];
            part[(wn * 128 + ra + 8) * 17 + c0]       = acc2m[mt][j][2];
            part[(wn * 128 + ra + 8) * 17 + c0 + 1]   = acc2m[mt][j][3];
        }
    }
    __syncthreads();

    // fused xl/xr: grp 0 -> xl, grp 1 -> xr
    {
        const int idx = row0 + r2;
        if (idx < nu) {
            const int node = g_perm[idx];
            float x10[FD];
            #pragma unroll
            for (int k = 0; k < FD; k++)
                x10[k] = part[r2 * 17 + k] + part[(128 + r2) * 17 + k] + b2[k];
            const float* W  = grp ? sWr : sWl;
            const float* bb = grp ? sbr : sbl;
            float o[HC];
            #pragma unroll
            for (int j = 0; j < HC; j++) {
                float a = bb[j];
                #pragma unroll
                for (int k = 0; k < FD; k++) a += x10[k] * W[k * HC + j];
                o[j] = a;
            }
            float* dst = grp ? &g_xr[(size_t)node * HC] : &g_xl[(size_t)node * HC];
            #pragma unroll
            for (int q = 0; q < 5; q++)
                *(float4*)&dst[q * 4] = make_float4(o[q*4], o[q*4+1], o[q*4+2], o[q*4+3]);
        }
    }
}

// ---------------- fused edge pass: alpha -> exp -> scatter num/den ----------------
__global__ void k_edge(const int* __restrict__ ei, const float* __restrict__ ew,
                       const float* __restrict__ We, const float* __restrict__ att)
{
    int e = blockIdx.x * blockDim.x + threadIdx.x;
    if (e >= EE) return;
    int src = ei[e], dst = ei[EE + e];
    float w = ew[e];
    const float4* xl4 = (const float4*)&g_xl[src * HC];
    const float4* xr4 = (const float4*)&g_xr[dst * HC];
    float xlv[HC];
    float a0 = 0.f, a1 = 0.f;
    #pragma unroll
    for (int q = 0; q < 5; q++) {
        float4 l = xl4[q], r = xr4[q];
        xlv[q * 4 + 0] = l.x; xlv[q * 4 + 1] = l.y;
        xlv[q * 4 + 2] = l.z; xlv[q * 4 + 3] = l.w;
        float vv[4] = { l.x + r.x, l.y + r.y, l.z + r.z, l.w + r.w };
        #pragma unroll
        for (int u = 0; u < 4; u++) {
            int j = q * 4 + u;
            float v = vv[u] + w * We[j];
            v = v > 0.f ? v : 0.2f * v;
            if (j < 10) a0 += v * att[j];
            else        a1 += v * att[j];
        }
    }
    float ex0 = __expf(a0), ex1 = __expf(a1);
    asm volatile("red.global.add.v2.f32 [%0], {%1,%2};"
                 :: "l"(&g_den[dst * 2]), "f"(ex0), "f"(ex1) : "memory");
    float* np = &g_num[dst * HC];
    #pragma unroll
    for (int q = 0; q < 5; q++) {
        float sx = (q * 4 + 0 < 10) ? ex0 : ex1;
        float sy = (q * 4 + 1 < 10) ? ex0 : ex1;
        float sz = (q * 4 + 2 < 10) ? ex0 : ex1;
        float sw = (q * 4 + 3 < 10) ? ex0 : ex1;
        float4 v = make_float4(xlv[q * 4] * sx, xlv[q * 4 + 1] * sy,
                               xlv[q * 4 + 2] * sz, xlv[q * 4 + 3] * sw);
        asm volatile("red.global.add.v4.f32 [%0], {%1,%2,%3,%4};"
                     :: "l"(np + q * 4), "f"(v.x), "f"(v.y), "f"(v.z), "f"(v.w)
                     : "memory");
    }
}

// =====================================================================
// kernel D: normalize -> +gat_bias -> GEMM3(mma) -> GEMM4(mma) -> out
// =====================================================================
#define A3_STRIDE 40
#define H_STRIDE  136
#define OFF_A3H   0
#define OFF_A3L   10240
#define OFF_HH2   20480
#define OFF_HL2   55296
#define SM2_TOTAL 90112

__global__ void __launch_bounds__(256, 1)
k_out_mma(const float* __restrict__ gat_bias,
          const float* __restrict__ b3, const float* __restrict__ b4,
          float* __restrict__ out)
{
    extern __shared__ char smem[];
    __nv_bfloat16* A3h = (__nv_bfloat16*)(smem + OFF_A3H);
    __nv_bfloat16* A3l = (__nv_bfloat16*)(smem + OFF_A3L);
    __nv_bfloat16* Hh  = (__nv_bfloat16*)(smem + OFF_HH2);
    __nv_bfloat16* Hl  = (__nv_bfloat16*)(smem + OFF_HL2);

    const int tid = threadIdx.x;
    const int lane = tid & 31;
    const int wid  = tid >> 5;
    const int wm = wid & 3, wn = wid >> 2;
    const int g = lane >> 2, q4 = lane & 3;
    const int row0 = blockIdx.x * 128;

    for (int i = tid; i < 128 * 32; i += 256) {
        int r = i >> 5, c = i & 31;
        A3h[r * A3_STRIDE + c] = __float2bfloat16(0.f);
        A3l[r * A3_STRIDE + c] = __float2bfloat16(0.f);
    }
    __syncthreads();
    for (int i = tid; i < 128 * HC; i += 256) {
        int r = i / HC, c = i % HC;
        int n = row0 + r;
        float v = 0.f;
        if (n < NN)
            v = g_num[(size_t)n * HC + c] / (g_den[n * 2 + c / 10] + 1e-16f) + gat_bias[c];
        __nv_bfloat16 h = __float2bfloat16(v);
        A3h[r * A3_STRIDE + c] = h;
        A3l[r * A3_STRIDE + c] = __float2bfloat16(v - __bfloat162float(h));
    }
    __syncthreads();

    float2 bw[8];
    #pragma unroll
    for (int j = 0; j < 8; j++)
        bw[j] = *(const float2*)&b4[wn * 64 + j * 8 + q4 * 2];

    float acc4[2][8][4];
    #pragma unroll
    for (int mt = 0; mt < 2; mt++)
        #pragma unroll
        for (int j = 0; j < 8; j++)
            #pragma unroll
            for (int c = 0; c < 4; c++) acc4[mt][j][c] = 0.f;

    const uint32_t a3h_s = smem_u32(A3h);
    const uint32_t a3l_s = smem_u32(A3l);
    const uint32_t hh_s  = smem_u32(Hh);
    const uint32_t hl_s  = smem_u32(Hl);
    const int lrow = lane & 15;
    const int lkb  = (lane >> 4) * 8;
    const uint32_t a3off0 = (uint32_t)(((wm * 32 + 0  + lrow) * A3_STRIDE + lkb) * 2);
    const uint32_t a3off1 = (uint32_t)(((wm * 32 + 16 + lrow) * A3_STRIDE + lkb) * 2);
    const uint32_t hoff0  = (uint32_t)(((wm * 32 + 0  + lrow) * H_STRIDE + lkb) * 2);
    const uint32_t hoff1  = (uint32_t)(((wm * 32 + 16 + lrow) * H_STRIDE + lkb) * 2);

    for (int nt = 0; nt < 4; nt++) {
        float acc3[2][8][4];
        #pragma unroll
        for (int mt = 0; mt < 2; mt++)
            #pragma unroll
            for (int j = 0; j < 8; j++)
                #pragma unroll
                for (int c = 0; c < 4; c++) acc3[mt][j][c] = 0.f;

        #pragma unroll
        for (int ks = 0; ks < 2; ks++) {
            uint32_t ah[2][4], al[2][4];
            ldsm_x4(ah[0], a3h_s + a3off0 + ks * 32);
            ldsm_x4(ah[1], a3h_s + a3off1 + ks * 32);
            ldsm_x4(al[0], a3l_s + a3off0 + ks * 32);
            ldsm_x4(al[1], a3l_s + a3off1 + ks * 32);
            #pragma unroll
            for (int j = 0; j < 8; j++) {
                int n8 = nt * 16 + wn * 8 + j;
                const uint4 bv = *(const uint4*)&g_w3frag[((n8 * 2 + ks) * 32 + lane) * 4];
                #pragma unroll
                for (int mt = 0; mt < 2; mt++) {
                    mma_bf16(acc3[mt][j], ah[mt], bv.x, bv.y);
                    mma_bf16(acc3[mt][j], ah[mt], bv.z, bv.w);
                    mma_bf16(acc3[mt][j], al[mt], bv.x, bv.y);
                }
            }
        }

        #pragma unroll
        for (int j = 0; j < 8; j++) {
            int hcol = nt * 128 + wn * 64 + j * 8 + q4 * 2;
            float2 bb = *(const float2*)&b3[hcol];
            int cl = wn * 64 + j * 8 + q4 * 2;
            #pragma unroll
            for (int mt = 0; mt < 2; mt++) {
                int ra = wm * 32 + mt * 16 + g;
                float v0 = acc3[mt][j][0] + bb.x;
                float v1 = acc3[mt][j][1] + bb.y;
                float v2 = acc3[mt][j][2] + bb.x;
                float v3 = acc3[mt][j][3] + bb.y;
                float h0 = __bfloat162float(__float2bfloat16(v0));
                float h1 = __bfloat162float(__float2bfloat16(v1));
                float h2 = __bfloat162float(__float2bfloat16(v2));
                float h3 = __bfloat162float(__float2bfloat16(v3));
                *(uint32_t*)&Hh[ra * H_STRIDE + cl]       = pk_bf2(h0, h1);
                *(uint32_t*)&Hh[(ra + 8) * H_STRIDE + cl] = pk_bf2(h2, h3);
                *(uint32_t*)&Hl[ra * H_STRIDE + cl]       = pk_bf2(v0 - h0, v1 - h1);
                *(uint32_t*)&Hl[(ra + 8) * H_STRIDE + cl] = pk_bf2(v2 - h2, v3 - h3);
            }
        }
        __syncthreads();

        #pragma unroll
        for (int ks = 0; ks < 8; ks++) {
            uint32_t ah[2][4], al[2][4];
            ldsm_x4(ah[0], hh_s + hoff0 + ks * 32);
            ldsm_x4(ah[1], hh_s + hoff1 + ks * 32);
            ldsm_x4(al[0], hl_s + hoff0 + ks * 32);
            ldsm_x4(al[1], hl_s + hoff1 + ks * 32);
            #pragma unroll
            for (int j = 0; j < 8; j++) {
                int n8 = wn * 8 + j;
                int ksg = nt * 8 + ks;
                const uint4 bv = *(const uint4*)&g_w4frag[((n8 * 32 + ksg) * 32 + lane) * 4];
                #pragma unroll
                for (int mt = 0; mt < 2; mt++) {
                    mma_bf16(acc4[mt][j], ah[mt], bv.x, bv.y);
                    mma_bf16(acc4[mt][j], ah[mt], bv.z, bv.w);
                    mma_bf16(acc4[mt][j], al[mt], bv.x, bv.y);
                }
            }
        }
        __syncthreads();
    }

    #pragma unroll
    for (int j = 0; j < 8; j++) {
        int col = wn * 64 + j * 8 + q4 * 2;
        #pragma unroll
        for (int mt = 0; mt < 2; mt++) {
            int ra = row0 + wm * 32 + mt * 16 + g;
            if (ra < NN)
                *(float2*)&out[(size_t)ra * CYD + col] =
                    make_float2(acc4[mt][j][0] + bw[j].x, acc4[mt][j][1] + bw[j].y);
            if (ra + 8 < NN)
                *(float2*)&out[(size_t)(ra + 8) * CYD + col] =
                    make_float2(acc4[mt][j][2] + bw[j].x, acc4[mt][j][3] + bw[j].y);
        }
    }
}

// ---------------- launch ----------------
extern "C" void kernel_launch(void* const* d_in, const int* in_sizes, int n_in,
                              void* d_out, int out_size)
{
    const float* signal = (const float*)d_in[0];
    const int*   ei     = (const int*)  d_in[1];
    const float* ew     = (const float*)d_in[2];
    const void*  mask   =               d_in[3];
    const float* W1 = (const float*)d_in[4];
    const float* b1 = (const float*)d_in[5];
    const float* ga = (const float*)d_in[6];
    const float* be = (const float*)d_in[7];
    const float* W2 = (const float*)d_in[8];
    const float* b2 = (const float*)d_in[9];
    const float* Wl = (const float*)d_in[10];
    const float* bl = (const float*)d_in[11];
    const float* Wr = (const float*)d_in[12];
    const float* br = (const float*)d_in[13];
    const float* We = (const float*)d_in[14];
    const float* att = (const float*)d_in[15];
    const float* gb  = (const float*)d_in[16];
    const float* W3 = (const float*)d_in[17];
    const float* b3 = (const float*)d_in[18];
    const float* W4 = (const float*)d_in[19];
    const float* b4 = (const float*)d_in[20];
    float* out = (float*)d_out;

    static uint32_t* w1f = nullptr;
    static uint32_t* w2f = nullptr;
    static uint32_t* w3f = nullptr;
    static uint32_t* w4f = nullptr;
    if (!w1f) {
        cudaGetSymbolAddress((void**)&w1f, g_w1frag);
        cudaGetSymbolAddress((void**)&w2f, g_w2frag);
        cudaGetSymbolAddress((void**)&w3f, g_w3frag);
        cudaGetSymbolAddress((void**)&w4f, g_w4frag);
        cudaFuncSetAttribute(k_mlp_mma, cudaFuncAttributeMaxDynamicSharedMemorySize, SM1_TOTAL);
        cudaFuncSetAttribute(k_out_mma, cudaFuncAttributeMaxDynamicSharedMemorySize, SM2_TOTAL);
    }

    k_detect<<<1, 256>>>((const unsigned*)mask);
    k_init<<<(NN * HC + 255) / 256, 256>>>();
    k_compact<<<(NN + 255) / 256, 256>>>(mask);
    k_prep<<<(H1 * CYD / 2 + 255) / 256, 256>>>(W1, w1f, CYD, CYD, H1);
    k_prep<<<(FD * H1 / 2 + 255) / 256, 256>>>(W2, w2f, H1, H1, FD);
    k_fill<<<120, 256>>>(b1, ga, be, W2, b2, Wl, bl, Wr, br);
    k_mlp_mma<<<(NN + 127) / 128, 256, SM1_TOTAL>>>(signal, b1, ga, be, b2,
                                                    Wl, bl, Wr, br);
    k_edge<<<(EE + 255) / 256, 256>>>(ei, ew, We, att);
    k_prep<<<(H2 * 32 / 2 + 255) / 256, 256>>>(W3, w3f, HC, 32, H2);
    k_prep<<<(CYD * H2 / 2 + 255) / 256, 256>>>(W4, w4f, H2, H2, CYD);
    k_out_mma<<<(NN + 127) / 128, 256, SM2_TOTAL>>>(gb, b3, b4, out);
}

// round 16
// speedup vs baseline: 1.5676x; 1.0084x over previous
#include <cuda_runtime.h>
#include <cuda_bf16.h>
#include <math_constants.h>
#include <cstdint>

#define NN      100000
#define EE      3200000
#define CYD     128
#define H1      512
#define FD      10
#define HC      20
#define H2      512

// ---------------- device scratch ----------------
__device__ float    g_xl[NN * HC];
__device__ float    g_xr[NN * HC];
__device__ float    g_den[NN * 2];
__device__ float    g_num[NN * HC];
__device__ int      g_mask_mode;
__device__ int      g_nu, g_nm;
__device__ int      g_perm[NN];
__device__ int      g_mlist[NN];
// fragment-packed weights: per (n8, ks, lane): {b0_hi, b1_hi, b0_lo, b1_lo}
__device__ uint32_t g_w1frag[(H1 / 8) * (CYD / 16) * 32 * 4];
__device__ uint32_t g_w2frag[(16 / 8) * (H1 / 16) * 32 * 4];   // W2: N pad 10->16, K=512
__device__ uint32_t g_w3frag[(H2 / 8) * (32 / 16) * 32 * 4];
__device__ uint32_t g_w4frag[(CYD / 8) * (H2 / 16) * 32 * 4];

// ---------------- helpers ----------------
__device__ __forceinline__ uint32_t pk_bf2(float a, float b) {
    __nv_bfloat162 h = __floats2bfloat162_rn(a, b);
    return *(uint32_t*)&h;
}
__device__ __forceinline__ void mma_bf16(float* c, const uint32_t* a, uint32_t b0, uint32_t b1) {
    asm volatile("mma.sync.aligned.m16n8k16.row.col.f32.bf16.bf16.f32 "
                 "{%0,%1,%2,%3}, {%4,%5,%6,%7}, {%8,%9}, {%0,%1,%2,%3};"
                 : "+f"(c[0]), "+f"(c[1]), "+f"(c[2]), "+f"(c[3])
                 : "r"(a[0]), "r"(a[1]), "r"(a[2]), "r"(a[3]), "r"(b0), "r"(b1));
}
__device__ __forceinline__ void ldsm_x4(uint32_t* r, uint32_t saddr) {
    asm volatile("ldmatrix.sync.aligned.m8n8.x4.shared.b16 {%0,%1,%2,%3}, [%4];"
                 : "=r"(r[0]), "=r"(r[1]), "=r"(r[2]), "=r"(r[3]) : "r"(saddr));
}
__device__ __forceinline__ uint32_t smem_u32(const void* p) {
    return (uint32_t)__cvta_generic_to_shared(p);
}

// ---------------- mask dtype detection ----------------
__global__ void k_detect(const unsigned* __restrict__ mw) {
    __shared__ int notInt, notFloat;
    if (threadIdx.x == 0) { notInt = 0; notFloat = 0; }
    __syncthreads();
    unsigned v = mw[threadIdx.x];
    if (v > 1u)                      atomicOr(&notInt, 1);
    if (v != 0u && v != 0x3f800000u) atomicOr(&notFloat, 1);
    __syncthreads();
    if (threadIdx.x == 0)
        g_mask_mode = notInt ? (notFloat ? 0 : 2) : 1;
}

// ---------------- init ----------------
__global__ void k_init() {
    int i = blockIdx.x * blockDim.x + threadIdx.x;
    if (i == 0) { g_nu = 0; g_nm = 0; }
    if (i < NN * HC) g_num[i] = 0.f;
    if (i < NN * 2) g_den[i] = 0.f;
}

// ---------------- node compaction (order-free) ----------------
__global__ void k_compact(const void* __restrict__ mask) {
    int i = blockIdx.x * blockDim.x + threadIdx.x;
    if (i >= NN) return;
    int mode = g_mask_mode;
    bool mk;
    if (mode == 0)      mk = ((const unsigned char*)mask)[i] != 0;
    else if (mode == 1) mk = ((const int*)mask)[i] != 0;
    else                mk = ((const float*)mask)[i] != 0.f;
    if (!mk) g_perm[atomicAdd(&g_nu, 1)] = i;
    else     g_mlist[atomicAdd(&g_nm, 1)] = i;
}

// ---------------- weight fragment prep ----------------
__global__ void k_prep(const float* __restrict__ W, uint32_t* __restrict__ frag,
                       int Kreal, int Kpad, int Nn)
{
    int i = blockIdx.x * blockDim.x + threadIdx.x;
    int kp2 = Kpad >> 1;
    if (i >= Nn * kp2) return;
    int n = i / kp2, k = (i % kp2) * 2;
    float w0 = (k     < Kreal) ? W[(size_t)k * Nn + n]       : 0.f;
    float w1 = (k + 1 < Kreal) ? W[(size_t)(k + 1) * Nn + n] : 0.f;
    float h0f = __bfloat162float(__float2bfloat16(w0));
    float h1f = __bfloat162float(__float2bfloat16(w1));
    uint32_t whi = pk_bf2(h0f, h1f);
    uint32_t wlo = pk_bf2(w0 - h0f, w1 - h1f);
    int n8 = n >> 3, ks = k >> 4;
    int lane = ((n & 7) << 2) | ((k & 7) >> 1);
    int b01 = (k >> 3) & 1;
    int base = ((n8 * (Kpad >> 4) + ks) * 32 + lane) * 4;
    frag[base + b01]     = whi;
    frag[base + 2 + b01] = wlo;
}

// ---------------- masked-node constant fill ----------------
__global__ void __launch_bounds__(256)
k_fill(const float* __restrict__ b1, const float* __restrict__ gamma,
       const float* __restrict__ beta, const float* __restrict__ W2,
       const float* __restrict__ b2,
       const float* __restrict__ Wl, const float* __restrict__ bl,
       const float* __restrict__ Wr, const float* __restrict__ br)
{
    __shared__ float sh[H1];
    __shared__ float sx2[FD];
    __shared__ __align__(16) float sout[2 * HC];
    const int t = threadIdx.x;
    const float inv = rsqrtf(1.f + 1e-5f);
    for (int h = t; h < H1; h += 256)
        sh[h] = fmaxf(b1[h] * gamma[h] * inv + beta[h], 0.f);
    __syncthreads();
    if (t < FD) {
        float a = b2[t];
        for (int h = 0; h < H1; h++) a += sh[h] * W2[h * FD + t];
        sx2[t] = a;
    }
    __syncthreads();
    if (t < 2 * HC) {
        int j = t % HC;
        bool left = t < HC;
        const float* W = left ? Wl : Wr;
        float a = left ? bl[j] : br[j];
        #pragma unroll
        for (int k = 0; k < FD; k++) a += sx2[k] * W[k * HC + j];
        sout[t] = a;
    }
    __syncthreads();
    const int nm = g_nm;
    for (int i = blockIdx.x * 256 + t; i < nm; i += gridDim.x * 256) {
        int node = g_mlist[i];
        float4* pl = (float4*)&g_xl[(size_t)node * HC];
        float4* pr = (float4*)&g_xr[(size_t)node * HC];
        #pragma unroll
        for (int q = 0; q < 5; q++) {
            pl[q] = *(float4*)&sout[q * 4];
            pr[q] = *(float4*)&sout[HC + q * 4];
        }
    }
}

// =====================================================================
// kernel A: compact rows -> GEMM1(mma) -> BN -> ReLU -> GEMM2(mma)
//           -> fused xl/xr epilogue
// =====================================================================
#define A_STRIDE 136
#define OFF_AHI  0
#define OFF_ALO  34816
#define OFF_HH   69632
#define OFF_HL   104448
#define OFF_B1   139264
#define OFF_SC   141312
#define OFF_BE   143360
#define OFF_WLR  145408
#define SM1_TOTAL 147200

__global__ void __launch_bounds__(256, 1)
k_mlp_mma(const float* __restrict__ signal,
          const float* __restrict__ b1,
          const float* __restrict__ gamma, const float* __restrict__ beta,
          const float* __restrict__ b2,
          const float* __restrict__ Wl, const float* __restrict__ bl,
          const float* __restrict__ Wr, const float* __restrict__ br)
{
    extern __shared__ char smem[];
    const int nu = g_nu;
    const int row0 = blockIdx.x * 128;
    if (row0 >= nu) return;

    __nv_bfloat16* Ahi = (__nv_bfloat16*)(smem + OFF_AHI);
    __nv_bfloat16* Alo = (__nv_bfloat16*)(smem + OFF_ALO);
    __nv_bfloat16* Hh  = (__nv_bfloat16*)(smem + OFF_HH);
    __nv_bfloat16* Hl  = (__nv_bfloat16*)(smem + OFF_HL);
    float*  sb1  = (float*)(smem + OFF_B1);
    float*  ssc  = (float*)(smem + OFF_SC);
    float*  sbe  = (float*)(smem + OFF_BE);
    float*  sWl  = (float*)(smem + OFF_WLR);
    float*  sWr  = sWl + 200;
    float*  sbl  = sWr + 200;
    float*  sbr  = sbl + 20;
    float*  part = (float*)(smem + OFF_HH);   // reused AFTER mainloop: [2][128][17]

    const int tid = threadIdx.x;
    const int lane = tid & 31;
    const int wid  = tid >> 5;
    const int wm = wid & 3, wn = wid >> 2;
    const int g  = lane >> 2, q4 = lane & 3;

    const float inv = rsqrtf(1.f + 1e-5f);
    for (int i = tid; i < H1; i += 256) {
        sb1[i] = b1[i];
        ssc[i] = gamma[i] * inv;
        sbe[i] = beta[i];
    }
    if (tid < 200) { sWl[tid] = Wl[tid]; sWr[tid] = Wr[tid]; }
    else if (tid < 220) sbl[tid - 200] = bl[tid - 200];
    else if (tid < 240) sbr[tid - 220] = br[tid - 220];

    // A: compacted rows -> smem bf16 hi/lo
    {
        const int r = tid >> 1, ch = tid & 1;
        const int idx = row0 + r;
        const bool ok = (idx < nu);
        const int n = ok ? g_perm[idx] : 0;
        const float4* xp = (const float4*)&signal[(size_t)n * CYD + ch * 64];
        #pragma unroll
        for (int qq = 0; qq < 8; qq++) {
            float4 v0 = ok ? xp[2 * qq]     : make_float4(0, 0, 0, 0);
            float4 v1 = ok ? xp[2 * qq + 1] : make_float4(0, 0, 0, 0);
            float f[8] = { v0.x, v0.y, v0.z, v0.w, v1.x, v1.y, v1.z, v1.w };
            float fh[8];
            #pragma unroll
            for (int u = 0; u < 8; u++) fh[u] = __bfloat162float(__float2bfloat16(f[u]));
            uint4 hi = make_uint4(pk_bf2(fh[0], fh[1]), pk_bf2(fh[2], fh[3]),
                                  pk_bf2(fh[4], fh[5]), pk_bf2(fh[6], fh[7]));
            uint4 lo = make_uint4(pk_bf2(f[0] - fh[0], f[1] - fh[1]), pk_bf2(f[2] - fh[2], f[3] - fh[3]),
                                  pk_bf2(f[4] - fh[4], f[5] - fh[5]), pk_bf2(f[6] - fh[6], f[7] - fh[7]));
            int eoff = r * A_STRIDE + ch * 64 + qq * 8;
            *(uint4*)&Ahi[eoff] = hi;
            *(uint4*)&Alo[eoff] = lo;
        }
    }
    __syncthreads();

    const int r2 = tid & 127, grp = tid >> 7;

    const uint32_t ahi_s = smem_u32(Ahi);
    const uint32_t alo_s = smem_u32(Alo);
    const uint32_t hh_s  = smem_u32(Hh);
    const uint32_t hl_s  = smem_u32(Hl);
    const int lrow = lane & 15;
    const int lkb  = (lane >> 4) * 8;
    const uint32_t aoff0 = (uint32_t)(((wm * 32 + 0  + lrow) * A_STRIDE + lkb) * 2);
    const uint32_t aoff1 = (uint32_t)(((wm * 32 + 16 + lrow) * A_STRIDE + lkb) * 2);

    float acc2m[2][2][4];
    #pragma unroll
    for (int mt = 0; mt < 2; mt++)
        #pragma unroll
        for (int j = 0; j < 2; j++)
            #pragma unroll
            for (int c = 0; c < 4; c++) acc2m[mt][j][c] = 0.f;

    for (int nt = 0; nt < 4; nt++) {
        float acc[2][8][4];
        #pragma unroll
        for (int mt = 0; mt < 2; mt++)
            #pragma unroll
            for (int j = 0; j < 8; j++)
                #pragma unroll
                for (int c = 0; c < 4; c++) acc[mt][j][c] = 0.f;

        #pragma unroll
        for (int ks = 0; ks < 8; ks++) {
            // batch all 8 B-fragment LDGs first (MLP=8; hide L2 latency)
            uint4 bvv[8];
            #pragma unroll
            for (int j = 0; j < 8; j++) {
                int n8 = nt * 16 + wn * 8 + j;
                bvv[j] = *(const uint4*)&g_w1frag[((n8 * 8 + ks) * 32 + lane) * 4];
            }
            uint32_t ah[2][4], al[2][4];
            ldsm_x4(ah[0], ahi_s + aoff0 + ks * 32);
            ldsm_x4(ah[1], ahi_s + aoff1 + ks * 32);
            ldsm_x4(al[0], alo_s + aoff0 + ks * 32);
            ldsm_x4(al[1], alo_s + aoff1 + ks * 32);
            #pragma unroll
            for (int j = 0; j < 8; j++) {
                #pragma unroll
                for (int mt = 0; mt < 2; mt++) {
                    mma_bf16(acc[mt][j], ah[mt], bvv[j].x, bvv[j].y);
                    mma_bf16(acc[mt][j], ah[mt], bvv[j].z, bvv[j].w);
                    mma_bf16(acc[mt][j], al[mt], bvv[j].x, bvv[j].y);
                }
            }
        }

        // epilogue: BN + ReLU -> split bf16 hi/lo into Hh/Hl (warp-private block)
        #pragma unroll
        for (int j = 0; j < 8; j++) {
            int hcol = nt * 128 + wn * 64 + j * 8 + q4 * 2;
            float s0 = ssc[hcol], s1 = ssc[hcol + 1];
            float bi0 = sb1[hcol], bi1 = sb1[hcol + 1];
            float be0 = sbe[hcol], be1 = sbe[hcol + 1];
            int cl = wn * 64 + j * 8 + q4 * 2;
            #pragma unroll
            for (int mt = 0; mt < 2; mt++) {
                int ra = wm * 32 + mt * 16 + g;
                float v0 = fmaxf((acc[mt][j][0] + bi0) * s0 + be0, 0.f);
                float v1 = fmaxf((acc[mt][j][1] + bi1) * s1 + be1, 0.f);
                float v2 = fmaxf((acc[mt][j][2] + bi0) * s0 + be0, 0.f);
                float v3 = fmaxf((acc[mt][j][3] + bi1) * s1 + be1, 0.f);
                float h0 = __bfloat162float(__float2bfloat16(v0));
                float h1 = __bfloat162float(__float2bfloat16(v1));
                float h2 = __bfloat162float(__float2bfloat16(v2));
                float h3 = __bfloat162float(__float2bfloat16(v3));
                *(uint32_t*)&Hh[ra * A_STRIDE + cl]       = pk_bf2(h0, h1);
                *(uint32_t*)&Hh[(ra + 8) * A_STRIDE + cl] = pk_bf2(h2, h3);
                *(uint32_t*)&Hl[ra * A_STRIDE + cl]       = pk_bf2(v0 - h0, v1 - h1);
                *(uint32_t*)&Hl[(ra + 8) * A_STRIDE + cl] = pk_bf2(v2 - h2, v3 - h3);
            }
        }
        __syncwarp();

        // GEMM2 mma: this warp's k-halves
        #pragma unroll
        for (int ks = 0; ks < 4; ks++) {
            const int kg = wn * 4 + ks;
            const int ksg = nt * 8 + kg;
            uint4 bvv[2];
            #pragma unroll
            for (int j = 0; j < 2; j++)
                bvv[j] = *(const uint4*)&g_w2frag[((j * 32 + ksg) * 32 + lane) * 4];
            uint32_t ah[2][4], al[2][4];
            const uint32_t ho = (uint32_t)((kg * 16 + lkb) * 2);
            ldsm_x4(ah[0], hh_s + aoff0 - lkb * 2 + ho);
            ldsm_x4(ah[1], hh_s + aoff1 - lkb * 2 + ho);
            ldsm_x4(al[0], hl_s + aoff0 - lkb * 2 + ho);
            ldsm_x4(al[1], hl_s + aoff1 - lkb * 2 + ho);
            #pragma unroll
            for (int j = 0; j < 2; j++) {
                #pragma unroll
                for (int mt = 0; mt < 2; mt++) {
                    mma_bf16(acc2m[mt][j], ah[mt], bvv[j].x, bvv[j].y);
                    mma_bf16(acc2m[mt][j], ah[mt], bvv[j].z, bvv[j].w);
                    mma_bf16(acc2m[mt][j], al[mt], bvv[j].x, bvv[j].y);
                }
            }
        }
        __syncwarp();
    }

    // combine wn partials: part[wn][row][17]
    __syncthreads();
    #pragma unroll
    for (int mt = 0; mt < 2; mt++) {
        #pragma unroll
        for (int j = 0; j < 2; j++) {
            int c0 = j * 8 + q4 * 2;
            int ra = wm * 32 + mt * 16 + g;
            part[(wn * 128 + ra) * 17 + c0]           = acc2m[mt][j][0];
            part[(wn * 128 + ra) * 17 + c0 + 1]       = acc2m[mt][j][1];
            part[(wn * 128 + ra + 8) * 17 + c0]       = acc2m[mt][j][2];
            part[(wn * 128 + ra + 8) * 17 + c0 + 1]   = acc2m[mt][j][3];
        }
    }
    __syncthreads();

    // fused xl/xr: grp 0 -> xl, grp 1 -> xr
    {
        const int idx = row0 + r2;
        if (idx < nu) {
            const int node = g_perm[idx];
            float x10[FD];
            #pragma unroll
            for (int k = 0; k < FD; k++)
                x10[k] = part[r2 * 17 + k] + part[(128 + r2) * 17 + k] + b2[k];
            const float* W  = grp ? sWr : sWl;
            const float* bb = grp ? sbr : sbl;
            float o[HC];
            #pragma unroll
            for (int j = 0; j < HC; j++) {
                float a = bb[j];
                #pragma unroll
                for (int k = 0; k < FD; k++) a += x10[k] * W[k * HC + j];
                o[j] = a;
            }
            float* dst = grp ? &g_xr[(size_t)node * HC] : &g_xl[(size_t)node * HC];
            #pragma unroll
            for (int q = 0; q < 5; q++)
                *(float4*)&dst[q * 4] = make_float4(o[q*4], o[q*4+1], o[q*4+2], o[q*4+3]);
        }
    }
}

// ---------------- fused edge pass ----------------
__global__ void k_edge(const int* __restrict__ ei, const float* __restrict__ ew,
                       const float* __restrict__ We, const float* __restrict__ att)
{
    int e = blockIdx.x * blockDim.x + threadIdx.x;
    if (e >= EE) return;
    int src = ei[e], dst = ei[EE + e];
    float w = ew[e];
    const float4* xl4 = (const float4*)&g_xl[src * HC];
    const float4* xr4 = (const float4*)&g_xr[dst * HC];
    float xlv[HC];
    float a0 = 0.f, a1 = 0.f;
    #pragma unroll
    for (int q = 0; q < 5; q++) {
        float4 l = xl4[q], r = xr4[q];
        xlv[q * 4 + 0] = l.x; xlv[q * 4 + 1] = l.y;
        xlv[q * 4 + 2] = l.z; xlv[q * 4 + 3] = l.w;
        float vv[4] = { l.x + r.x, l.y + r.y, l.z + r.z, l.w + r.w };
        #pragma unroll
        for (int u = 0; u < 4; u++) {
            int j = q * 4 + u;
            float v = vv[u] + w * We[j];
            v = v > 0.f ? v : 0.2f * v;
            if (j < 10) a0 += v * att[j];
            else        a1 += v * att[j];
        }
    }
    float ex0 = __expf(a0), ex1 = __expf(a1);
    asm volatile("red.global.add.v2.f32 [%0], {%1,%2};"
                 :: "l"(&g_den[dst * 2]), "f"(ex0), "f"(ex1) : "memory");
    float* np = &g_num[dst * HC];
    #pragma unroll
    for (int q = 0; q < 5; q++) {
        float sx = (q * 4 + 0 < 10) ? ex0 : ex1;
        float sy = (q * 4 + 1 < 10) ? ex0 : ex1;
        float sz = (q * 4 + 2 < 10) ? ex0 : ex1;
        float sw = (q * 4 + 3 < 10) ? ex0 : ex1;
        float4 v = make_float4(xlv[q * 4] * sx, xlv[q * 4 + 1] * sy,
                               xlv[q * 4 + 2] * sz, xlv[q * 4 + 3] * sw);
        asm volatile("red.global.add.v4.f32 [%0], {%1,%2,%3,%4};"
                     :: "l"(np + q * 4), "f"(v.x), "f"(v.y), "f"(v.z), "f"(v.w)
                     : "memory");
    }
}

// =====================================================================
// kernel D: normalize -> +gat_bias -> GEMM3(mma) -> GEMM4(mma) -> out
// =====================================================================
#define A3_STRIDE 40
#define H_STRIDE  136
#define OFF_A3H   0
#define OFF_A3L   10240
#define OFF_HH2   20480
#define OFF_HL2   55296
#define SM2_TOTAL 90112

__global__ void __launch_bounds__(256, 1)
k_out_mma(const float* __restrict__ gat_bias,
          const float* __restrict__ b3, const float* __restrict__ b4,
          float* __restrict__ out)
{
    extern __shared__ char smem[];
    __nv_bfloat16* A3h = (__nv_bfloat16*)(smem + OFF_A3H);
    __nv_bfloat16* A3l = (__nv_bfloat16*)(smem + OFF_A3L);
    __nv_bfloat16* Hh  = (__nv_bfloat16*)(smem + OFF_HH2);
    __nv_bfloat16* Hl  = (__nv_bfloat16*)(smem + OFF_HL2);

    const int tid = threadIdx.x;
    const int lane = tid & 31;
    const int wid  = tid >> 5;
    const int wm = wid & 3, wn = wid >> 2;
    const int g = lane >> 2, q4 = lane & 3;
    const int row0 = blockIdx.x * 128;

    for (int i = tid; i < 128 * 32; i += 256) {
        int r = i >> 5, c = i & 31;
        A3h[r * A3_STRIDE + c] = __float2bfloat16(0.f);
        A3l[r * A3_STRIDE + c] = __float2bfloat16(0.f);
    }
    __syncthreads();
    for (int i = tid; i < 128 * HC; i += 256) {
        int r = i / HC, c = i % HC;
        int n = row0 + r;
        float v = 0.f;
        if (n < NN)
            v = g_num[(size_t)n * HC + c] / (g_den[n * 2 + c / 10] + 1e-16f) + gat_bias[c];
        __nv_bfloat16 h = __float2bfloat16(v);
        A3h[r * A3_STRIDE + c] = h;
        A3l[r * A3_STRIDE + c] = __float2bfloat16(v - __bfloat162float(h));
    }
    __syncthreads();

    float2 bw[8];
    #pragma unroll
    for (int j = 0; j < 8; j++)
        bw[j] = *(const float2*)&b4[wn * 64 + j * 8 + q4 * 2];

    float acc4[2][8][4];
    #pragma unroll
    for (int mt = 0; mt < 2; mt++)
        #pragma unroll
        for (int j = 0; j < 8; j++)
            #pragma unroll
            for (int c = 0; c < 4; c++) acc4[mt][j][c] = 0.f;

    const uint32_t a3h_s = smem_u32(A3h);
    const uint32_t a3l_s = smem_u32(A3l);
    const uint32_t hh_s  = smem_u32(Hh);
    const uint32_t hl_s  = smem_u32(Hl);
    const int lrow = lane & 15;
    const int lkb  = (lane >> 4) * 8;
    const uint32_t a3off0 = (uint32_t)(((wm * 32 + 0  + lrow) * A3_STRIDE + lkb) * 2);
    const uint32_t a3off1 = (uint32_t)(((wm * 32 + 16 + lrow) * A3_STRIDE + lkb) * 2);
    const uint32_t hoff0  = (uint32_t)(((wm * 32 + 0  + lrow) * H_STRIDE + lkb) * 2);
    const uint32_t hoff1  = (uint32_t)(((wm * 32 + 16 + lrow) * H_STRIDE + lkb) * 2);

    for (int nt = 0; nt < 4; nt++) {
        float acc3[2][8][4];
        #pragma unroll
        for (int mt = 0; mt < 2; mt++)
            #pragma unroll
            for (int j = 0; j < 8; j++)
                #pragma unroll
                for (int c = 0; c < 4; c++) acc3[mt][j][c] = 0.f;

        #pragma unroll
        for (int ks = 0; ks < 2; ks++) {
            uint4 bvv[8];
            #pragma unroll
            for (int j = 0; j < 8; j++) {
                int n8 = nt * 16 + wn * 8 + j;
                bvv[j] = *(const uint4*)&g_w3frag[((n8 * 2 + ks) * 32 + lane) * 4];
            }
            uint32_t ah[2][4], al[2][4];
            ldsm_x4(ah[0], a3h_s + a3off0 + ks * 32);
            ldsm_x4(ah[1], a3h_s + a3off1 + ks * 32);
            ldsm_x4(al[0], a3l_s + a3off0 + ks * 32);
            ldsm_x4(al[1], a3l_s + a3off1 + ks * 32);
            #pragma unroll
            for (int j = 0; j < 8; j++) {
                #pragma unroll
                for (int mt = 0; mt < 2; mt++) {
                    mma_bf16(acc3[mt][j], ah[mt], bvv[j].x, bvv[j].y);
                    mma_bf16(acc3[mt][j], ah[mt], bvv[j].z, bvv[j].w);
                    mma_bf16(acc3[mt][j], al[mt], bvv[j].x, bvv[j].y);
                }
            }
        }

        #pragma unroll
        for (int j = 0; j < 8; j++) {
            int hcol = nt * 128 + wn * 64 + j * 8 + q4 * 2;
            float2 bb = *(const float2*)&b3[hcol];
            int cl = wn * 64 + j * 8 + q4 * 2;
            #pragma unroll
            for (int mt = 0; mt < 2; mt++) {
                int ra = wm * 32 + mt * 16 + g;
                float v0 = acc3[mt][j][0] + bb.x;
                float v1 = acc3[mt][j][1] + bb.y;
                float v2 = acc3[mt][j][2] + bb.x;
                float v3 = acc3[mt][j][3] + bb.y;
                float h0 = __bfloat162float(__float2bfloat16(v0));
                float h1 = __bfloat162float(__float2bfloat16(v1));
                float h2 = __bfloat162float(__float2bfloat16(v2));
                float h3 = __bfloat162float(__float2bfloat16(v3));
                *(uint32_t*)&Hh[ra * H_STRIDE + cl]       = pk_bf2(h0, h1);
                *(uint32_t*)&Hh[(ra + 8) * H_STRIDE + cl] = pk_bf2(h2, h3);
                *(uint32_t*)&Hl[ra * H_STRIDE + cl]       = pk_bf2(v0 - h0, v1 - h1);
                *(uint32_t*)&Hl[(ra + 8) * H_STRIDE + cl] = pk_bf2(v2 - h2, v3 - h3);
            }
        }
        __syncthreads();

        #pragma unroll
        for (int ks = 0; ks < 8; ks++) {
            uint4 bvv[8];
            const int ksg = nt * 8 + ks;
            #pragma unroll
            for (int j = 0; j < 8; j++) {
                int n8 = wn * 8 + j;
                bvv[j] = *(const uint4*)&g_w4frag[((n8 * 32 + ksg) * 32 + lane) * 4];
            }
            uint32_t ah[2][4], al[2][4];
            ldsm_x4(ah[0], hh_s + hoff0 + ks * 32);
            ldsm_x4(ah[1], hh_s + hoff1 + ks * 32);
            ldsm_x4(al[0], hl_s + hoff0 + ks * 32);
            ldsm_x4(al[1], hl_s + hoff1 + ks * 32);
            #pragma unroll
            for (int j = 0; j < 8; j++) {
                #pragma unroll
                for (int mt = 0; mt < 2; mt++) {
                    mma_bf16(acc4[mt][j], ah[mt], bvv[j].x, bvv[j].y);
                    mma_bf16(acc4[mt][j], ah[mt], bvv[j].z, bvv[j].w);
                    mma_bf16(acc4[mt][j], al[mt], bvv[j].x, bvv[j].y);
                }
            }
        }
        __syncthreads();
    }

    #pragma unroll
    for (int j = 0; j < 8; j++) {
        int col = wn * 64 + j * 8 + q4 * 2;
        #pragma unroll
        for (int mt = 0; mt < 2; mt++) {
            int ra = row0 + wm * 32 + mt * 16 + g;
            if (ra < NN)
                *(float2*)&out[(size_t)ra * CYD + col] =
                    make_float2(acc4[mt][j][0] + bw[j].x, acc4[mt][j][1] + bw[j].y);
            if (ra + 8 < NN)
                *(float2*)&out[(size_t)(ra + 8) * CYD + col] =
                    make_float2(acc4[mt][j][2] + bw[j].x, acc4[mt][j][3] + bw[j].y);
        }
    }
}

// ---------------- launch ----------------
extern "C" void kernel_launch(void* const* d_in, const int* in_sizes, int n_in,
                              void* d_out, int out_size)
{
    const float* signal = (const float*)d_in[0];
    const int*   ei     = (const int*)  d_in[1];
    const float* ew     = (const float*)d_in[2];
    const void*  mask   =               d_in[3];
    const float* W1 = (const float*)d_in[4];
    const float* b1 = (const float*)d_in[5];
    const float* ga = (const float*)d_in[6];
    const float* be = (const float*)d_in[7];
    const float* W2 = (const float*)d_in[8];
    const float* b2 = (const float*)d_in[9];
    const float* Wl = (const float*)d_in[10];
    const float* bl = (const float*)d_in[11];
    const float* Wr = (const float*)d_in[12];
    const float* br = (const float*)d_in[13];
    const float* We = (const float*)d_in[14];
    const float* att = (const float*)d_in[15];
    const float* gb  = (const float*)d_in[16];
    const float* W3 = (const float*)d_in[17];
    const float* b3 = (const float*)d_in[18];
    const float* W4 = (const float*)d_in[19];
    const float* b4 = (const float*)d_in[20];
    float* out = (float*)d_out;

    static uint32_t* w1f = nullptr;
    static uint32_t* w2f = nullptr;
    static uint32_t* w3f = nullptr;
    static uint32_t* w4f = nullptr;
    if (!w1f) {
        cudaGetSymbolAddress((void**)&w1f, g_w1frag);
        cudaGetSymbolAddress((void**)&w2f, g_w2frag);
        cudaGetSymbolAddress((void**)&w3f, g_w3frag);
        cudaGetSymbolAddress((void**)&w4f, g_w4frag);
        cudaFuncSetAttribute(k_mlp_mma, cudaFuncAttributeMaxDynamicSharedMemorySize, SM1_TOTAL);
        cudaFuncSetAttribute(k_out_mma, cudaFuncAttributeMaxDynamicSharedMemorySize, SM2_TOTAL);
    }

    k_detect<<<1, 256>>>((const unsigned*)mask);
    k_init<<<(NN * HC + 255) / 256, 256>>>();
    k_compact<<<(NN + 255) / 256, 256>>>(mask);
    k_prep<<<(H1 * CYD / 2 + 255) / 256, 256>>>(W1, w1f, CYD, CYD, H1);
    k_prep<<<(FD * H1 / 2 + 255) / 256, 256>>>(W2, w2f, H1, H1, FD);
    k_fill<<<120, 256>>>(b1, ga, be, W2, b2, Wl, bl, Wr, br);
    k_mlp_mma<<<(NN + 127) / 128, 256, SM1_TOTAL>>>(signal, b1, ga, be, b2,
                                                    Wl, bl, Wr, br);
    k_edge<<<(EE + 255) / 256, 256>>>(ei, ew, We, att);
    k_prep<<<(H2 * 32 / 2 + 255) / 256, 256>>>(W3, w3f, HC, 32, H2);
    k_prep<<<(CYD * H2 / 2 + 255) / 256, 256>>>(W4, w4f, H2, H2, CYD);
    k_out_mma<<<(NN + 127) / 128, 256, SM2_TOTAL>>>(gb, b3, b4, out);
}

// round 17
// speedup vs baseline: 1.6091x; 1.0264x over previous
#include <cuda_runtime.h>
#include <cuda_bf16.h>
#include <math_constants.h>
#include <cstdint>

#define NN      100000
#define EE      3200000
#define CYD     128
#define H1      512
#define FD      10
#define HC      20
#define H2      512

// ---------------- device scratch ----------------
__device__ float    g_xl[NN * HC];
__device__ float    g_xr[NN * HC];
__device__ float    g_den[NN * 2];
__device__ float    g_num[NN * HC];
__device__ int      g_mask_mode;
__device__ int      g_nu, g_nm;
__device__ int      g_perm[NN];
__device__ int      g_mlist[NN];
// fragment-packed weights: per (n8, ks, lane): {b0_hi, b1_hi, b0_lo, b1_lo}
__device__ uint32_t g_w1frag[(H1 / 8) * (CYD / 16) * 32 * 4];
__device__ uint32_t g_w2frag[(16 / 8) * (H1 / 16) * 32 * 4];
__device__ uint32_t g_w3frag[(H2 / 8) * (32 / 16) * 32 * 4];
__device__ uint32_t g_w4frag[(CYD / 8) * (H2 / 16) * 32 * 4];

// ---------------- helpers ----------------
__device__ __forceinline__ uint32_t pk_bf2(float a, float b) {
    __nv_bfloat162 h = __floats2bfloat162_rn(a, b);
    return *(uint32_t*)&h;
}
__device__ __forceinline__ void mma_bf16(float* c, const uint32_t* a, uint32_t b0, uint32_t b1) {
    asm volatile("mma.sync.aligned.m16n8k16.row.col.f32.bf16.bf16.f32 "
                 "{%0,%1,%2,%3}, {%4,%5,%6,%7}, {%8,%9}, {%0,%1,%2,%3};"
                 : "+f"(c[0]), "+f"(c[1]), "+f"(c[2]), "+f"(c[3])
                 : "r"(a[0]), "r"(a[1]), "r"(a[2]), "r"(a[3]), "r"(b0), "r"(b1));
}
__device__ __forceinline__ void ldsm_x4(uint32_t* r, uint32_t saddr) {
    asm volatile("ldmatrix.sync.aligned.m8n8.x4.shared.b16 {%0,%1,%2,%3}, [%4];"
                 : "=r"(r[0]), "=r"(r[1]), "=r"(r[2]), "=r"(r[3]) : "r"(saddr));
}
__device__ __forceinline__ uint32_t smem_u32(const void* p) {
    return (uint32_t)__cvta_generic_to_shared(p);
}

// ---------------- mask dtype detection ----------------
__global__ void k_detect(const unsigned* __restrict__ mw) {
    __shared__ int notInt, notFloat;
    if (threadIdx.x == 0) { notInt = 0; notFloat = 0; }
    __syncthreads();
    unsigned v = mw[threadIdx.x];
    if (v > 1u)                      atomicOr(&notInt, 1);
    if (v != 0u && v != 0x3f800000u) atomicOr(&notFloat, 1);
    __syncthreads();
    if (threadIdx.x == 0)
        g_mask_mode = notInt ? (notFloat ? 0 : 2) : 1;
}

// ---------------- init ----------------
__global__ void k_init() {
    int i = blockIdx.x * blockDim.x + threadIdx.x;
    if (i == 0) { g_nu = 0; g_nm = 0; }
    if (i < NN * HC) g_num[i] = 0.f;
    if (i < NN * 2) g_den[i] = 0.f;
}

// ---------------- node compaction (order-free) ----------------
__global__ void k_compact(const void* __restrict__ mask) {
    int i = blockIdx.x * blockDim.x + threadIdx.x;
    if (i >= NN) return;
    int mode = g_mask_mode;
    bool mk;
    if (mode == 0)      mk = ((const unsigned char*)mask)[i] != 0;
    else if (mode == 1) mk = ((const int*)mask)[i] != 0;
    else                mk = ((const float*)mask)[i] != 0.f;
    if (!mk) g_perm[atomicAdd(&g_nu, 1)] = i;
    else     g_mlist[atomicAdd(&g_nm, 1)] = i;
}

// ---------------- weight fragment prep ----------------
__global__ void k_prep(const float* __restrict__ W, uint32_t* __restrict__ frag,
                       int Kreal, int Kpad, int Nn)
{
    int i = blockIdx.x * blockDim.x + threadIdx.x;
    int kp2 = Kpad >> 1;
    if (i >= Nn * kp2) return;
    int n = i / kp2, k = (i % kp2) * 2;
    float w0 = (k     < Kreal) ? W[(size_t)k * Nn + n]       : 0.f;
    float w1 = (k + 1 < Kreal) ? W[(size_t)(k + 1) * Nn + n] : 0.f;
    float h0f = __bfloat162float(__float2bfloat16(w0));
    float h1f = __bfloat162float(__float2bfloat16(w1));
    uint32_t whi = pk_bf2(h0f, h1f);
    uint32_t wlo = pk_bf2(w0 - h0f, w1 - h1f);
    int n8 = n >> 3, ks = k >> 4;
    int lane = ((n & 7) << 2) | ((k & 7) >> 1);
    int b01 = (k >> 3) & 1;
    int base = ((n8 * (Kpad >> 4) + ks) * 32 + lane) * 4;
    frag[base + b01]     = whi;
    frag[base + 2 + b01] = wlo;
}

// ---------------- masked-node constant fill ----------------
__global__ void __launch_bounds__(256)
k_fill(const float* __restrict__ b1, const float* __restrict__ gamma,
       const float* __restrict__ beta, const float* __restrict__ W2,
       const float* __restrict__ b2,
       const float* __restrict__ Wl, const float* __restrict__ bl,
       const float* __restrict__ Wr, const float* __restrict__ br)
{
    __shared__ float sh[H1];
    __shared__ float sx2[FD];
    __shared__ __align__(16) float sout[2 * HC];
    const int t = threadIdx.x;
    const float inv = rsqrtf(1.f + 1e-5f);
    for (int h = t; h < H1; h += 256)
        sh[h] = fmaxf(b1[h] * gamma[h] * inv + beta[h], 0.f);
    __syncthreads();
    if (t < FD) {
        float a = b2[t];
        for (int h = 0; h < H1; h++) a += sh[h] * W2[h * FD + t];
        sx2[t] = a;
    }
    __syncthreads();
    if (t < 2 * HC) {
        int j = t % HC;
        bool left = t < HC;
        const float* W = left ? Wl : Wr;
        float a = left ? bl[j] : br[j];
        #pragma unroll
        for (int k = 0; k < FD; k++) a += sx2[k] * W[k * HC + j];
        sout[t] = a;
    }
    __syncthreads();
    const int nm = g_nm;
    for (int i = blockIdx.x * 256 + t; i < nm; i += gridDim.x * 256) {
        int node = g_mlist[i];
        float4* pl = (float4*)&g_xl[(size_t)node * HC];
        float4* pr = (float4*)&g_xr[(size_t)node * HC];
        #pragma unroll
        for (int q = 0; q < 5; q++) {
            pl[q] = *(float4*)&sout[q * 4];
            pr[q] = *(float4*)&sout[HC + q * 4];
        }
    }
}

// =====================================================================
// kernel A: 512 threads, 16 warps (8 m-stripes x 2 n-halves)
// compact rows -> GEMM1(mma) -> BN -> ReLU -> GEMM2(mma) -> xl/xr
// =====================================================================
#define A_STRIDE 136
#define OFF_AHI  0
#define OFF_ALO  34816
#define OFF_HH   69632
#define OFF_HL   104448
#define OFF_B1   139264
#define OFF_SC   141312
#define OFF_BE   143360
#define OFF_WLR  145408
#define SM1_TOTAL 147200

__global__ void __launch_bounds__(512, 1)
k_mlp_mma(const float* __restrict__ signal,
          const float* __restrict__ b1,
          const float* __restrict__ gamma, const float* __restrict__ beta,
          const float* __restrict__ b2,
          const float* __restrict__ Wl, const float* __restrict__ bl,
          const float* __restrict__ Wr, const float* __restrict__ br)
{
    extern __shared__ char smem[];
    const int nu = g_nu;
    const int row0 = blockIdx.x * 128;
    if (row0 >= nu) return;

    __nv_bfloat16* Ahi = (__nv_bfloat16*)(smem + OFF_AHI);
    __nv_bfloat16* Alo = (__nv_bfloat16*)(smem + OFF_ALO);
    __nv_bfloat16* Hh  = (__nv_bfloat16*)(smem + OFF_HH);
    __nv_bfloat16* Hl  = (__nv_bfloat16*)(smem + OFF_HL);
    float*  sb1  = (float*)(smem + OFF_B1);
    float*  ssc  = (float*)(smem + OFF_SC);
    float*  sbe  = (float*)(smem + OFF_BE);
    float*  sWl  = (float*)(smem + OFF_WLR);
    float*  sWr  = sWl + 200;
    float*  sbl  = sWr + 200;
    float*  sbr  = sbl + 20;
    float*  part = (float*)(smem + OFF_HH);   // reused AFTER mainloop: [2][128][17]

    const int tid = threadIdx.x;
    const int lane = tid & 31;
    const int wid  = tid >> 5;
    const int wm = wid & 7, wn = wid >> 3;     // 8 m-stripes x 2 n-halves
    const int g  = lane >> 2, q4 = lane & 3;

    const float inv = rsqrtf(1.f + 1e-5f);
    for (int i = tid; i < H1; i += 512) {
        sb1[i] = b1[i];
        ssc[i] = gamma[i] * inv;
        sbe[i] = beta[i];
    }
    if (tid < 200) { sWl[tid] = Wl[tid]; sWr[tid] = Wr[tid]; }
    else if (tid < 220) sbl[tid - 200] = bl[tid - 200];
    else if (tid < 240) sbr[tid - 220] = br[tid - 220];

    // A: compacted rows -> smem bf16 hi/lo (4 threads per row: 2 ch x 2 halves)
    {
        const int r = tid >> 2, ch = (tid >> 1) & 1, hf = tid & 1;
        const int idx = row0 + r;
        const bool ok = (idx < nu);
        const int n = ok ? g_perm[idx] : 0;
        const float4* xp = (const float4*)&signal[(size_t)n * CYD + ch * 64];
        #pragma unroll
        for (int q2 = 0; q2 < 4; q2++) {
            int qq = hf * 4 + q2;
            float4 v0 = ok ? xp[2 * qq]     : make_float4(0, 0, 0, 0);
            float4 v1 = ok ? xp[2 * qq + 1] : make_float4(0, 0, 0, 0);
            float f[8] = { v0.x, v0.y, v0.z, v0.w, v1.x, v1.y, v1.z, v1.w };
            float fh[8];
            #pragma unroll
            for (int u = 0; u < 8; u++) fh[u] = __bfloat162float(__float2bfloat16(f[u]));
            uint4 hi = make_uint4(pk_bf2(fh[0], fh[1]), pk_bf2(fh[2], fh[3]),
                                  pk_bf2(fh[4], fh[5]), pk_bf2(fh[6], fh[7]));
            uint4 lo = make_uint4(pk_bf2(f[0] - fh[0], f[1] - fh[1]), pk_bf2(f[2] - fh[2], f[3] - fh[3]),
                                  pk_bf2(f[4] - fh[4], f[5] - fh[5]), pk_bf2(f[6] - fh[6], f[7] - fh[7]));
            int eoff = r * A_STRIDE + ch * 64 + qq * 8;
            *(uint4*)&Ahi[eoff] = hi;
            *(uint4*)&Alo[eoff] = lo;
        }
    }
    __syncthreads();

    const uint32_t ahi_s = smem_u32(Ahi);
    const uint32_t alo_s = smem_u32(Alo);
    const uint32_t hh_s  = smem_u32(Hh);
    const uint32_t hl_s  = smem_u32(Hl);
    const int lrow = lane & 15;
    const int lkb  = (lane >> 4) * 8;
    const uint32_t aoff  = (uint32_t)(((wm * 16 + lrow) * A_STRIDE + lkb) * 2);
    const uint32_t hbase = (uint32_t)(((wm * 16 + lrow) * A_STRIDE) * 2);

    float acc2m[2][4];
    #pragma unroll
    for (int j = 0; j < 2; j++)
        #pragma unroll
        for (int c = 0; c < 4; c++) acc2m[j][c] = 0.f;

    for (int nt = 0; nt < 4; nt++) {
        float acc[8][4];
        #pragma unroll
        for (int j = 0; j < 8; j++)
            #pragma unroll
            for (int c = 0; c < 4; c++) acc[j][c] = 0.f;

        #pragma unroll
        for (int ks = 0; ks < 8; ks++) {
            uint4 bvv[8];
            #pragma unroll
            for (int j = 0; j < 8; j++) {
                int n8 = nt * 16 + wn * 8 + j;
                bvv[j] = *(const uint4*)&g_w1frag[((n8 * 8 + ks) * 32 + lane) * 4];
            }
            uint32_t ah[4], al[4];
            ldsm_x4(ah, ahi_s + aoff + ks * 32);
            ldsm_x4(al, alo_s + aoff + ks * 32);
            #pragma unroll
            for (int j = 0; j < 8; j++) {
                mma_bf16(acc[j], ah, bvv[j].x, bvv[j].y);
                mma_bf16(acc[j], ah, bvv[j].z, bvv[j].w);
                mma_bf16(acc[j], al, bvv[j].x, bvv[j].y);
            }
        }

        // epilogue: BN + ReLU -> split bf16 hi/lo into Hh/Hl (warp-private rows)
        #pragma unroll
        for (int j = 0; j < 8; j++) {
            int hcol = nt * 128 + wn * 64 + j * 8 + q4 * 2;
            float s0 = ssc[hcol], s1 = ssc[hcol + 1];
            float bi0 = sb1[hcol], bi1 = sb1[hcol + 1];
            float be0 = sbe[hcol], be1 = sbe[hcol + 1];
            int cl = wn * 64 + j * 8 + q4 * 2;
            int ra = wm * 16 + g;
            float v0 = fmaxf((acc[j][0] + bi0) * s0 + be0, 0.f);
            float v1 = fmaxf((acc[j][1] + bi1) * s1 + be1, 0.f);
            float v2 = fmaxf((acc[j][2] + bi0) * s0 + be0, 0.f);
            float v3 = fmaxf((acc[j][3] + bi1) * s1 + be1, 0.f);
            float h0 = __bfloat162float(__float2bfloat16(v0));
            float h1 = __bfloat162float(__float2bfloat16(v1));
            float h2 = __bfloat162float(__float2bfloat16(v2));
            float h3 = __bfloat162float(__float2bfloat16(v3));
            *(uint32_t*)&Hh[ra * A_STRIDE + cl]       = pk_bf2(h0, h1);
            *(uint32_t*)&Hh[(ra + 8) * A_STRIDE + cl] = pk_bf2(h2, h3);
            *(uint32_t*)&Hl[ra * A_STRIDE + cl]       = pk_bf2(v0 - h0, v1 - h1);
            *(uint32_t*)&Hl[(ra + 8) * A_STRIDE + cl] = pk_bf2(v2 - h2, v3 - h3);
        }
        __syncwarp();

        // GEMM2 mma: this warp's k-halves (wn selects 64 of 128 local cols)
        #pragma unroll
        for (int ks = 0; ks < 4; ks++) {
            const int kg = wn * 4 + ks;
            const int ksg = nt * 8 + kg;
            uint4 bvv[2];
            #pragma unroll
            for (int j = 0; j < 2; j++)
                bvv[j] = *(const uint4*)&g_w2frag[((j * 32 + ksg) * 32 + lane) * 4];
            uint32_t ah[4], al[4];
            const uint32_t ho = (uint32_t)((kg * 16 + lkb) * 2);
            ldsm_x4(ah, hh_s + hbase + ho);
            ldsm_x4(al, hl_s + hbase + ho);
            #pragma unroll
            for (int j = 0; j < 2; j++) {
                mma_bf16(acc2m[j], ah, bvv[j].x, bvv[j].y);
                mma_bf16(acc2m[j], ah, bvv[j].z, bvv[j].w);
                mma_bf16(acc2m[j], al, bvv[j].x, bvv[j].y);
            }
        }
        __syncwarp();
    }

    // combine wn partials: part[wn][row][17]
    __syncthreads();
    #pragma unroll
    for (int j = 0; j < 2; j++) {
        int c0 = j * 8 + q4 * 2;
        int ra = wm * 16 + g;
        part[(wn * 128 + ra) * 17 + c0]           = acc2m[j][0];
        part[(wn * 128 + ra) * 17 + c0 + 1]       = acc2m[j][1];
        part[(wn * 128 + ra + 8) * 17 + c0]       = acc2m[j][2];
        part[(wn * 128 + ra + 8) * 17 + c0 + 1]   = acc2m[j][3];
    }
    __syncthreads();

    // fused xl/xr: first 256 threads (grp 0 -> xl, grp 1 -> xr)
    if (tid < 256) {
        const int r2 = tid & 127, grp = tid >> 7;
        const int idx = row0 + r2;
        if (idx < nu) {
            const int node = g_perm[idx];
            float x10[FD];
            #pragma unroll
            for (int k = 0; k < FD; k++)
                x10[k] = part[r2 * 17 + k] + part[(128 + r2) * 17 + k] + b2[k];
            const float* W  = grp ? sWr : sWl;
            const float* bb = grp ? sbr : sbl;
            float o[HC];
            #pragma unroll
            for (int j = 0; j < HC; j++) {
                float a = bb[j];
                #pragma unroll
                for (int k = 0; k < FD; k++) a += x10[k] * W[k * HC + j];
                o[j] = a;
            }
            float* dst = grp ? &g_xr[(size_t)node * HC] : &g_xl[(size_t)node * HC];
            #pragma unroll
            for (int q = 0; q < 5; q++)
                *(float4*)&dst[q * 4] = make_float4(o[q*4], o[q*4+1], o[q*4+2], o[q*4+3]);
        }
    }
}

// ---------------- fused edge pass ----------------
__global__ void k_edge(const int* __restrict__ ei, const float* __restrict__ ew,
                       const float* __restrict__ We, const float* __restrict__ att)
{
    int e = blockIdx.x * blockDim.x + threadIdx.x;
    if (e >= EE) return;
    int src = ei[e], dst = ei[EE + e];
    float w = ew[e];
    const float4* xl4 = (const float4*)&g_xl[src * HC];
    const float4* xr4 = (const float4*)&g_xr[dst * HC];
    float xlv[HC];
    float a0 = 0.f, a1 = 0.f;
    #pragma unroll
    for (int q = 0; q < 5; q++) {
        float4 l = xl4[q], r = xr4[q];
        xlv[q * 4 + 0] = l.x; xlv[q * 4 + 1] = l.y;
        xlv[q * 4 + 2] = l.z; xlv[q * 4 + 3] = l.w;
        float vv[4] = { l.x + r.x, l.y + r.y, l.z + r.z, l.w + r.w };
        #pragma unroll
        for (int u = 0; u < 4; u++) {
            int j = q * 4 + u;
            float v = vv[u] + w * We[j];
            v = v > 0.f ? v : 0.2f * v;
            if (j < 10) a0 += v * att[j];
            else        a1 += v * att[j];
        }
    }
    float ex0 = __expf(a0), ex1 = __expf(a1);
    asm volatile("red.global.add.v2.f32 [%0], {%1,%2};"
                 :: "l"(&g_den[dst * 2]), "f"(ex0), "f"(ex1) : "memory");
    float* np = &g_num[dst * HC];
    #pragma unroll
    for (int q = 0; q < 5; q++) {
        float sx = (q * 4 + 0 < 10) ? ex0 : ex1;
        float sy = (q * 4 + 1 < 10) ? ex0 : ex1;
        float sz = (q * 4 + 2 < 10) ? ex0 : ex1;
        float sw = (q * 4 + 3 < 10) ? ex0 : ex1;
        float4 v = make_float4(xlv[q * 4] * sx, xlv[q * 4 + 1] * sy,
                               xlv[q * 4 + 2] * sz, xlv[q * 4 + 3] * sw);
        asm volatile("red.global.add.v4.f32 [%0], {%1,%2,%3,%4};"
                     :: "l"(np + q * 4), "f"(v.x), "f"(v.y), "f"(v.z), "f"(v.w)
                     : "memory");
    }
}

// =====================================================================
// kernel D: 512 threads, 16 warps (8 m-stripes x 2 n-halves)
// normalize -> +gat_bias -> GEMM3(mma) -> GEMM4(mma) -> out
// =====================================================================
#define A3_STRIDE 40
#define H_STRIDE  136
#define OFF_A3H   0
#define OFF_A3L   10240
#define OFF_HH2   20480
#define OFF_HL2   55296
#define SM2_TOTAL 90112

__global__ void __launch_bounds__(512, 1)
k_out_mma(const float* __restrict__ gat_bias,
          const float* __restrict__ b3, const float* __restrict__ b4,
          float* __restrict__ out)
{
    extern __shared__ char smem[];
    __nv_bfloat16* A3h = (__nv_bfloat16*)(smem + OFF_A3H);
    __nv_bfloat16* A3l = (__nv_bfloat16*)(smem + OFF_A3L);
    __nv_bfloat16* Hh  = (__nv_bfloat16*)(smem + OFF_HH2);
    __nv_bfloat16* Hl  = (__nv_bfloat16*)(smem + OFF_HL2);

    const int tid = threadIdx.x;
    const int lane = tid & 31;
    const int wid  = tid >> 5;
    const int wm = wid & 7, wn = wid >> 3;
    const int g = lane >> 2, q4 = lane & 3;
    const int row0 = blockIdx.x * 128;

    for (int i = tid; i < 128 * 32; i += 512) {
        int r = i >> 5, c = i & 31;
        A3h[r * A3_STRIDE + c] = __float2bfloat16(0.f);
        A3l[r * A3_STRIDE + c] = __float2bfloat16(0.f);
    }
    __syncthreads();
    for (int i = tid; i < 128 * HC; i += 512) {
        int r = i / HC, c = i % HC;
        int n = row0 + r;
        float v = 0.f;
        if (n < NN)
            v = g_num[(size_t)n * HC + c] / (g_den[n * 2 + c / 10] + 1e-16f) + gat_bias[c];
        __nv_bfloat16 h = __float2bfloat16(v);
        A3h[r * A3_STRIDE + c] = h;
        A3l[r * A3_STRIDE + c] = __float2bfloat16(v - __bfloat162float(h));
    }
    __syncthreads();

    float2 bw[8];
    #pragma unroll
    for (int j = 0; j < 8; j++)
        bw[j] = *(const float2*)&b4[wn * 64 + j * 8 + q4 * 2];

    float acc4[8][4];
    #pragma unroll
    for (int j = 0; j < 8; j++)
        #pragma unroll
        for (int c = 0; c < 4; c++) acc4[j][c] = 0.f;

    const uint32_t a3h_s = smem_u32(A3h);
    const uint32_t a3l_s = smem_u32(A3l);
    const uint32_t hh_s  = smem_u32(Hh);
    const uint32_t hl_s  = smem_u32(Hl);
    const int lrow = lane & 15;
    const int lkb  = (lane >> 4) * 8;
    const uint32_t a3off = (uint32_t)(((wm * 16 + lrow) * A3_STRIDE + lkb) * 2);
    const uint32_t hoff  = (uint32_t)(((wm * 16 + lrow) * H_STRIDE + lkb) * 2);

    for (int nt = 0; nt < 4; nt++) {
        float acc3[8][4];
        #pragma unroll
        for (int j = 0; j < 8; j++)
            #pragma unroll
            for (int c = 0; c < 4; c++) acc3[j][c] = 0.f;

        #pragma unroll
        for (int ks = 0; ks < 2; ks++) {
            uint4 bvv[8];
            #pragma unroll
            for (int j = 0; j < 8; j++) {
                int n8 = nt * 16 + wn * 8 + j;
                bvv[j] = *(const uint4*)&g_w3frag[((n8 * 2 + ks) * 32 + lane) * 4];
            }
            uint32_t ah[4], al[4];
            ldsm_x4(ah, a3h_s + a3off + ks * 32);
            ldsm_x4(al, a3l_s + a3off + ks * 32);
            #pragma unroll
            for (int j = 0; j < 8; j++) {
                mma_bf16(acc3[j], ah, bvv[j].x, bvv[j].y);
                mma_bf16(acc3[j], ah, bvv[j].z, bvv[j].w);
                mma_bf16(acc3[j], al, bvv[j].x, bvv[j].y);
            }
        }

        #pragma unroll
        for (int j = 0; j < 8; j++) {
            int hcol = nt * 128 + wn * 64 + j * 8 + q4 * 2;
            float2 bb = *(const float2*)&b3[hcol];
            int cl = wn * 64 + j * 8 + q4 * 2;
            int ra = wm * 16 + g;
            float v0 = acc3[j][0] + bb.x;
            float v1 = acc3[j][1] + bb.y;
            float v2 = acc3[j][2] + bb.x;
            float v3 = acc3[j][3] + bb.y;
            float h0 = __bfloat162float(__float2bfloat16(v0));
            float h1 = __bfloat162float(__float2bfloat16(v1));
            float h2 = __bfloat162float(__float2bfloat16(v2));
            float h3 = __bfloat162float(__float2bfloat16(v3));
            *(uint32_t*)&Hh[ra * H_STRIDE + cl]       = pk_bf2(h0, h1);
            *(uint32_t*)&Hh[(ra + 8) * H_STRIDE + cl] = pk_bf2(h2, h3);
            *(uint32_t*)&Hl[ra * H_STRIDE + cl]       = pk_bf2(v0 - h0, v1 - h1);
            *(uint32_t*)&Hl[(ra + 8) * H_STRIDE + cl] = pk_bf2(v2 - h2, v3 - h3);
        }
        __syncthreads();

        #pragma unroll
        for (int ks = 0; ks < 8; ks++) {
            uint4 bvv[8];
            const int ksg = nt * 8 + ks;
            #pragma unroll
            for (int j = 0; j < 8; j++) {
                int n8 = wn * 8 + j;
                bvv[j] = *(const uint4*)&g_w4frag[((n8 * 32 + ksg) * 32 + lane) * 4];
            }
            uint32_t ah[4], al[4];
            ldsm_x4(ah, hh_s + hoff + ks * 32);
            ldsm_x4(al, hl_s + hoff + ks * 32);
            #pragma unroll
            for (int j = 0; j < 8; j++) {
                mma_bf16(acc4[j], ah, bvv[j].x, bvv[j].y);
                mma_bf16(acc4[j], ah, bvv[j].z, bvv[j].w);
                mma_bf16(acc4[j], al, bvv[j].x, bvv[j].y);
            }
        }
        __syncthreads();
    }

    #pragma unroll
    for (int j = 0; j < 8; j++) {
        int col = wn * 64 + j * 8 + q4 * 2;
        int ra = row0 + wm * 16 + g;
        if (ra < NN)
            *(float2*)&out[(size_t)ra * CYD + col] =
                make_float2(acc4[j][0] + bw[j].x, acc4[j][1] + bw[j].y);
        if (ra + 8 < NN)
            *(float2*)&out[(size_t)(ra + 8) * CYD + col] =
                make_float2(acc4[j][2] + bw[j].x, acc4[j][3] + bw[j].y);
    }
}

// ---------------- launch ----------------
extern "C" void kernel_launch(void* const* d_in, const int* in_sizes, int n_in,
                              void* d_out, int out_size)
{
    const float* signal = (const float*)d_in[0];
    const int*   ei     = (const int*)  d_in[1];
    const float* ew     = (const float*)d_in[2];
    const void*  mask   =               d_in[3];
    const float* W1 = (const float*)d_in[4];
    const float* b1 = (const float*)d_in[5];
    const float* ga = (const float*)d_in[6];
    const float* be = (const float*)d_in[7];
    const float* W2 = (const float*)d_in[8];
    const float* b2 = (const float*)d_in[9];
    const float* Wl = (const float*)d_in[10];
    const float* bl = (const float*)d_in[11];
    const float* Wr = (const float*)d_in[12];
    const float* br = (const float*)d_in[13];
    const float* We = (const float*)d_in[14];
    const float* att = (const float*)d_in[15];
    const float* gb  = (const float*)d_in[16];
    const float* W3 = (const float*)d_in[17];
    const float* b3 = (const float*)d_in[18];
    const float* W4 = (const float*)d_in[19];
    const float* b4 = (const float*)d_in[20];
    float* out = (float*)d_out;

    static uint32_t* w1f = nullptr;
    static uint32_t* w2f = nullptr;
    static uint32_t* w3f = nullptr;
    static uint32_t* w4f = nullptr;
    if (!w1f) {
        cudaGetSymbolAddress((void**)&w1f, g_w1frag);
        cudaGetSymbolAddress((void**)&w2f, g_w2frag);
        cudaGetSymbolAddress((void**)&w3f, g_w3frag);
        cudaGetSymbolAddress((void**)&w4f, g_w4frag);
        cudaFuncSetAttribute(k_mlp_mma, cudaFuncAttributeMaxDynamicSharedMemorySize, SM1_TOTAL);
        cudaFuncSetAttribute(k_out_mma, cudaFuncAttributeMaxDynamicSharedMemorySize, SM2_TOTAL);
    }

    k_detect<<<1, 256>>>((const unsigned*)mask);
    k_init<<<(NN * HC + 255) / 256, 256>>>();
    k_compact<<<(NN + 255) / 256, 256>>>(mask);
    k_prep<<<(H1 * CYD / 2 + 255) / 256, 256>>>(W1, w1f, CYD, CYD, H1);
    k_prep<<<(FD * H1 / 2 + 255) / 256, 256>>>(W2, w2f, H1, H1, FD);
    k_fill<<<120, 256>>>(b1, ga, be, W2, b2, Wl, bl, Wr, br);
    k_mlp_mma<<<(NN + 127) / 128, 512, SM1_TOTAL>>>(signal, b1, ga, be, b2,
                                                    Wl, bl, Wr, br);
    k_edge<<<(EE + 255) / 256, 256>>>(ei, ew, We, att);
    k_prep<<<(H2 * 32 / 2 + 255) / 256, 256>>>(W3, w3f, HC, 32, H2);
    k_prep<<<(CYD * H2 / 2 + 255) / 256, 256>>>(W4, w4f, H2, H2, CYD);
    k_out_mma<<<(NN + 127) / 128, 512, SM2_TOTAL>>>(gb, b3, b4, out);
}